// round 2
// baseline (speedup 1.0000x reference)
#include <cuda_runtime.h>
#include <math.h>

#define BATCH   2
#define SEQ     2048
#define DMODEL  1024
#define NHEADS  16
#define HDIM    64
#define MTOT    (BATCH*SEQ)           // 4096
#define LOG2_THETA 13.28771238f       // log2(10000)

// Scratch (allocation-free rule: __device__ globals). 16MB each.
__device__ float g_Q[BATCH*NHEADS*SEQ*HDIM];
__device__ float g_K[BATCH*NHEADS*SEQ*HDIM];
__device__ float g_V[BATCH*NHEADS*SEQ*HDIM];
__device__ float g_attn[MTOT*DMODEL];

// ---------------------------------------------------------------------------
// GEMM: C = A @ W^T.  A: [M, K] row-major, W: [N, K] row-major.
// Tile 64x64, BK=16, 256 threads, 4x4 microtile per thread.
// MODE 0: plain row-major output [M, N]          (output projection)
// MODE 1: RoPE + head-split layout [b,h,s,hd]    (Q, K)
// MODE 2: head-split layout, no RoPE             (V)
// ---------------------------------------------------------------------------
template<int MODE>
__global__ __launch_bounds__(256)
void gemm_kernel(const float* __restrict__ A, const float* __restrict__ W,
                 float* __restrict__ out, const int* __restrict__ posarr)
{
    const int K = DMODEL, N = DMODEL;
    __shared__ float As[16][64];   // [k][m] transposed
    __shared__ float Ws[16][64];   // [k][n] transposed

    const int tid = threadIdx.x;
    const int m0 = blockIdx.y * 64;
    const int n0 = blockIdx.x * 64;
    const int tx = tid & 15;       // n microtile
    const int ty = tid >> 4;       // m microtile
    const int lr = tid >> 2;       // 0..63  load row
    const int lc4 = tid & 3;       // 0..3   load float4 col

    float acc[4][4];
    #pragma unroll
    for (int i = 0; i < 4; i++)
        #pragma unroll
        for (int j = 0; j < 4; j++) acc[i][j] = 0.f;

    const float* Arow = A + (size_t)(m0 + lr) * K + lc4 * 4;
    const float* Wrow = W + (size_t)(n0 + lr) * K + lc4 * 4;

    for (int k0 = 0; k0 < K; k0 += 16) {
        float4 av = *(const float4*)(Arow + k0);
        float4 wv = *(const float4*)(Wrow + k0);
        As[lc4*4+0][lr] = av.x; As[lc4*4+1][lr] = av.y;
        As[lc4*4+2][lr] = av.z; As[lc4*4+3][lr] = av.w;
        Ws[lc4*4+0][lr] = wv.x; Ws[lc4*4+1][lr] = wv.y;
        Ws[lc4*4+2][lr] = wv.z; Ws[lc4*4+3][lr] = wv.w;
        __syncthreads();
        #pragma unroll
        for (int k = 0; k < 16; k++) {
            float4 a = *(const float4*)&As[k][ty*4];
            float4 b = *(const float4*)&Ws[k][tx*4];
            acc[0][0] += a.x*b.x; acc[0][1] += a.x*b.y; acc[0][2] += a.x*b.z; acc[0][3] += a.x*b.w;
            acc[1][0] += a.y*b.x; acc[1][1] += a.y*b.y; acc[1][2] += a.y*b.z; acc[1][3] += a.y*b.w;
            acc[2][0] += a.z*b.x; acc[2][1] += a.z*b.y; acc[2][2] += a.z*b.z; acc[2][3] += a.z*b.w;
            acc[3][0] += a.w*b.x; acc[3][1] += a.w*b.y; acc[3][2] += a.w*b.z; acc[3][3] += a.w*b.w;
        }
        __syncthreads();
    }

    if (MODE == 0) {
        #pragma unroll
        for (int i = 0; i < 4; i++) {
            float4 v = make_float4(acc[i][0], acc[i][1], acc[i][2], acc[i][3]);
            *(float4*)&out[(size_t)(m0 + ty*4 + i) * N + n0 + tx*4] = v;
        }
    } else {
        // n-tile spans exactly one head (64 cols)
        const int h   = n0 >> 6;
        const int hd0 = tx * 4;          // even, so pairs stay within microtile
        if (MODE == 1) {
            const float freq0 = exp2f(-LOG2_THETA * (2.0f * (float)(tx*2    )) / 64.0f);
            const float freq1 = exp2f(-LOG2_THETA * (2.0f * (float)(tx*2 + 1)) / 64.0f);
            #pragma unroll
            for (int i = 0; i < 4; i++) {
                int m = m0 + ty*4 + i;
                int b = m >> 11;
                int s = m & (SEQ - 1);
                float pos = (float)posarr[s];
                float* o = out + (((size_t)(b*NHEADS + h) * SEQ + s) * HDIM) + hd0;
                float sn0, cs0, sn1, cs1;
                sincosf(pos * freq0, &sn0, &cs0);
                sincosf(pos * freq1, &sn1, &cs1);
                float4 v;
                v.x = acc[i][0]*cs0 - acc[i][1]*sn0;
                v.y = acc[i][0]*sn0 + acc[i][1]*cs0;
                v.z = acc[i][2]*cs1 - acc[i][3]*sn1;
                v.w = acc[i][2]*sn1 + acc[i][3]*cs1;
                *(float4*)o = v;
            }
        } else { // MODE 2
            #pragma unroll
            for (int i = 0; i < 4; i++) {
                int m = m0 + ty*4 + i;
                int b = m >> 11;
                int s = m & (SEQ - 1);
                float4 v = make_float4(acc[i][0], acc[i][1], acc[i][2], acc[i][3]);
                *(float4*)&out[(((size_t)(b*NHEADS + h) * SEQ + s) * HDIM) + hd0] = v;
            }
        }
    }
}

// ---------------------------------------------------------------------------
// Causal flash attention, fp32. Q/K/V in [b*h, S, 64] layout.
// Block: 64 threads = 64 query rows. grid = (S/64, B*H).
// Per thread: q row (scaled) + 64-wide accumulator in registers.
// ---------------------------------------------------------------------------
__global__ __launch_bounds__(64)
void attn_kernel(const float* __restrict__ Q, const float* __restrict__ K,
                 const float* __restrict__ V, float* __restrict__ out)
{
    __shared__ float Ks[64][64];
    __shared__ float Vs[64][64];

    const int bh = blockIdx.y;          // 0..31
    const int qb = blockIdx.x;          // 0..31
    const int t  = threadIdx.x;         // 0..63
    const int qi = qb * 64 + t;

    const float* Qb = Q + (size_t)bh * SEQ * HDIM;
    const float* Kb = K + (size_t)bh * SEQ * HDIM;
    const float* Vb = V + (size_t)bh * SEQ * HDIM;

    // load + pre-scale q row into registers (1/sqrt(64) = 0.125)
    float q[64];
    {
        const float* qrow = Qb + (size_t)qi * HDIM;
        #pragma unroll
        for (int d4 = 0; d4 < 16; d4++) {
            float4 v = *(const float4*)(qrow + d4*4);
            q[d4*4+0] = v.x * 0.125f; q[d4*4+1] = v.y * 0.125f;
            q[d4*4+2] = v.z * 0.125f; q[d4*4+3] = v.w * 0.125f;
        }
    }

    float acc[64];
    #pragma unroll
    for (int d = 0; d < 64; d++) acc[d] = 0.f;
    float mmax = -INFINITY, l = 0.f;

    for (int kb = 0; kb <= qb; kb++) {
        // cooperative coalesced tile load: row p, col t
        #pragma unroll 4
        for (int p = 0; p < 64; p++) {
            Ks[p][t] = Kb[((size_t)(kb*64 + p)) * HDIM + t];
            Vs[p][t] = Vb[((size_t)(kb*64 + p)) * HDIM + t];
        }
        __syncthreads();

        const int jmax = (kb == qb) ? (t + 1) : 64;
        for (int j = 0; j < jmax; j++) {
            float s = 0.f;
            #pragma unroll
            for (int d4 = 0; d4 < 16; d4++) {
                float4 kk = *(const float4*)&Ks[j][d4*4];   // broadcast
                s += q[d4*4+0]*kk.x + q[d4*4+1]*kk.y
                   + q[d4*4+2]*kk.z + q[d4*4+3]*kk.w;
            }
            if (s > mmax) {
                float f = __expf(mmax - s);
                l *= f;
                #pragma unroll
                for (int d = 0; d < 64; d++) acc[d] *= f;
                mmax = s;
            }
            float p = __expf(s - mmax);
            l += p;
            #pragma unroll
            for (int d4 = 0; d4 < 16; d4++) {
                float4 vv = *(const float4*)&Vs[j][d4*4];   // broadcast
                acc[d4*4+0] += p * vv.x; acc[d4*4+1] += p * vv.y;
                acc[d4*4+2] += p * vv.z; acc[d4*4+3] += p * vv.w;
            }
        }
        __syncthreads();
    }

    // write to [b, s, D] layout for the output projection
    const int b = bh / NHEADS;
    const int h = bh % NHEADS;
    float inv = 1.0f / l;
    float* o = out + ((size_t)(b * SEQ + qi)) * DMODEL + h * HDIM;
    #pragma unroll
    for (int d4 = 0; d4 < 16; d4++) {
        float4 v = make_float4(acc[d4*4+0]*inv, acc[d4*4+1]*inv,
                               acc[d4*4+2]*inv, acc[d4*4+3]*inv);
        *(float4*)(o + d4*4) = v;
    }
}

// ---------------------------------------------------------------------------
extern "C" void kernel_launch(void* const* d_in, const int* in_sizes, int n_in,
                              void* d_out, int out_size)
{
    const float* x   = (const float*)d_in[0];
    const float* Wq  = (const float*)d_in[1];
    const float* Wk  = (const float*)d_in[2];
    const float* Wv  = (const float*)d_in[3];
    const float* Wo  = (const float*)d_in[4];
    // d_in[5] = causal mask (implicit via kernel), d_in[6] = token positions
    const int* pos   = (const int*)d_in[6];
    float* out       = (float*)d_out;

    float *gQ, *gK, *gV, *gA;
    cudaGetSymbolAddress((void**)&gQ, g_Q);
    cudaGetSymbolAddress((void**)&gK, g_K);
    cudaGetSymbolAddress((void**)&gV, g_V);
    cudaGetSymbolAddress((void**)&gA, g_attn);

    dim3 gg(DMODEL/64, MTOT/64);   // (16, 64)
    gemm_kernel<1><<<gg, 256>>>(x, Wq, gQ, pos);
    gemm_kernel<1><<<gg, 256>>>(x, Wk, gK, pos);
    gemm_kernel<2><<<gg, 256>>>(x, Wv, gV, nullptr);

    dim3 ga(SEQ/64, BATCH*NHEADS); // (32, 32)
    attn_kernel<<<ga, 64>>>(gQ, gK, gV, gA);

    gemm_kernel<0><<<gg, 256>>>(gA, Wo, out, nullptr);
}

// round 4
// speedup vs baseline: 1.5696x; 1.5696x over previous
#include <cuda_runtime.h>
#include <cuda_bf16.h>
#include <math.h>
#include <stdint.h>

#define BATCH   2
#define SEQ     2048
#define DMODEL  1024
#define NHEADS  16
#define HDIM    64
#define MTOT    (BATCH*SEQ)           // 4096
#define LOG2_THETA 13.28771238f       // log2(10000)

// ---- HMMA GEMM tiling ----
#define BM 128
#define BN 128
#define BKE 64                         // K elems per chunk
#define PITCHE 72                      // padded smem row (elems)
#define ROWB (PITCHE*2)                // 144 bytes per row
#define TILE_B (128*ROWB)              // 18432 bytes (A and B tiles both 128 rows)
#define STAGE_B (4*TILE_B)             // Ah, Al, Bh, Bl = 73728
#define SMEM_TOTAL (2*STAGE_B)         // double buffered = 147456

// ---- scratch (__device__ globals; no allocs allowed) ----
__device__ float g_Q[BATCH*NHEADS*SEQ*HDIM];
__device__ float g_K[BATCH*NHEADS*SEQ*HDIM];
__device__ float g_V[BATCH*NHEADS*SEQ*HDIM];
__device__ float g_attn[MTOT*DMODEL];
__device__ __nv_bfloat16 g_xh[MTOT*DMODEL], g_xl[MTOT*DMODEL];
__device__ __nv_bfloat16 g_wh[4][DMODEL*DMODEL], g_wl[4][DMODEL*DMODEL];
__device__ __nv_bfloat16 g_ah[MTOT*DMODEL], g_al[MTOT*DMODEL];

// ---------------------------------------------------------------------------
// PTX helpers (sm_80-era instructions only; no tcgen05 on this toolchain)
// ---------------------------------------------------------------------------
__device__ __forceinline__ uint32_t smem_u32(const void* p) {
    uint32_t a;
    asm("{ .reg .u64 t; cvta.to.shared.u64 t, %1; cvt.u32.u64 %0, t; }" : "=r"(a) : "l"(p));
    return a;
}
#define CP16(s, g)  asm volatile("cp.async.cg.shared.global [%0], [%1], 16;" :: "r"(s), "l"(g))
#define CPCOMMIT()  asm volatile("cp.async.commit_group;" ::: "memory")
#define CPWAIT0()   asm volatile("cp.async.wait_group 0;" ::: "memory")
#define CPWAIT1()   asm volatile("cp.async.wait_group 1;" ::: "memory")

#define LDMX4(r, a) asm volatile("ldmatrix.sync.aligned.m8n8.x4.shared.b16 {%0,%1,%2,%3}, [%4];" \
    : "=r"((r)[0]), "=r"((r)[1]), "=r"((r)[2]), "=r"((r)[3]) : "r"(a))
#define LDMX2(r, a) asm volatile("ldmatrix.sync.aligned.m8n8.x2.shared.b16 {%0,%1}, [%2];" \
    : "=r"((r)[0]), "=r"((r)[1]) : "r"(a))

#define MMA16816(c, a, b) asm volatile( \
    "mma.sync.aligned.m16n8k16.row.col.f32.bf16.bf16.f32 " \
    "{%0,%1,%2,%3},{%4,%5,%6,%7},{%8,%9},{%0,%1,%2,%3};" \
    : "+f"((c)[0]), "+f"((c)[1]), "+f"((c)[2]), "+f"((c)[3]) \
    : "r"((a)[0]), "r"((a)[1]), "r"((a)[2]), "r"((a)[3]), "r"((b)[0]), "r"((b)[1]))

// ---------------------------------------------------------------------------
// fp32 -> (hi,lo) bf16 split conversion
// ---------------------------------------------------------------------------
__global__ __launch_bounds__(256)
void split_f32(const float* __restrict__ in, __nv_bfloat16* __restrict__ hi,
               __nv_bfloat16* __restrict__ lo, int n4)
{
    int i = blockIdx.x * 256 + threadIdx.x;
    if (i >= n4) return;
    float4 v = ((const float4*)in)[i];
    __nv_bfloat16 h0 = __float2bfloat16(v.x), h1 = __float2bfloat16(v.y);
    __nv_bfloat16 h2 = __float2bfloat16(v.z), h3 = __float2bfloat16(v.w);
    __nv_bfloat16 l0 = __float2bfloat16(v.x - __bfloat162float(h0));
    __nv_bfloat16 l1 = __float2bfloat16(v.y - __bfloat162float(h1));
    __nv_bfloat16 l2 = __float2bfloat16(v.z - __bfloat162float(h2));
    __nv_bfloat16 l3 = __float2bfloat16(v.w - __bfloat162float(h3));
    __nv_bfloat162 hA = {h0, h1}, hB = {h2, h3}, lA = {l0, l1}, lB = {l2, l3};
    uint2 uh, ul;
    uh.x = *(uint32_t*)&hA; uh.y = *(uint32_t*)&hB;
    ul.x = *(uint32_t*)&lA; ul.y = *(uint32_t*)&lB;
    ((uint2*)hi)[i] = uh;
    ((uint2*)lo)[i] = ul;
}

// ---------------------------------------------------------------------------
// split-bf16 HMMA GEMM: C = A @ W^T.  A[4096,1024], W[1024,1024], both K-major.
// 128x128 tile, BK=64, cp.async double buffer, 8 warps (2m x 4n), warp 64x32.
// 3 MMA terms: Ah*Bh + Ah*Bl + Al*Bh, fp32 accum.
// MODE 0: [M,1024] row-major; MODE 1: RoPE + [b,h,s,d]; MODE 2: [b,h,s,d]
// ---------------------------------------------------------------------------
template<int MODE>
__global__ __launch_bounds__(256)
void gemm_mma(const __nv_bfloat16* __restrict__ Ahi, const __nv_bfloat16* __restrict__ Alo,
              const __nv_bfloat16* __restrict__ Bhi, const __nv_bfloat16* __restrict__ Blo,
              float* __restrict__ out, const int* __restrict__ posarr)
{
    extern __shared__ char smem[];
    const uint32_t sb = smem_u32(smem);
    const int tid  = threadIdx.x;
    const int warp = tid >> 5;
    const int lane = tid & 31;
    const int m0 = blockIdx.y * BM;
    const int n0 = blockIdx.x * BN;
    const int wm0 = (warp >> 2) * 64;    // 0 / 64
    const int wn0 = (warp & 3) * 32;     // 0/32/64/96

    float acc[4][4][4];
    #pragma unroll
    for (int i = 0; i < 4; i++)
        #pragma unroll
        for (int j = 0; j < 4; j++)
            #pragma unroll
            for (int k = 0; k < 4; k++) acc[i][j][k] = 0.f;

    const __nv_bfloat16* srcs[4] = {
        Ahi + (size_t)m0 * DMODEL, Alo + (size_t)m0 * DMODEL,
        Bhi + (size_t)n0 * DMODEL, Blo + (size_t)n0 * DMODEL
    };

    // issue one stage: 4 tiles x 128 rows x 64 elems = 4096 x 16B vectors
    auto issue = [&](int buf, int chunk) {
        const int kof = chunk * BKE;
        #pragma unroll
        for (int t = 0; t < 16; t++) {
            int j = t * 256 + tid;
            int tile = j >> 10;
            int v = j & 1023;
            int row = v >> 3, c = v & 7;
            const __nv_bfloat16* g = srcs[tile] + (size_t)row * DMODEL + kof + c * 8;
            uint32_t s = sb + buf * STAGE_B + tile * TILE_B + row * ROWB + c * 16;
            CP16(s, g);
        }
        CPCOMMIT();
    };

    issue(0, 0);

    for (int i = 0; i < 16; i++) {
        if (i < 15) { issue((i + 1) & 1, i + 1); CPWAIT1(); }
        else        { CPWAIT0(); }
        __syncthreads();

        const uint32_t base = sb + (i & 1) * STAGE_B;
        #pragma unroll
        for (int ks = 0; ks < 4; ks++) {
            uint32_t ah[4][4], al[4][4], bh[4][2], bl[4][2];
            const int arow = wm0 + (lane & 15);
            const int acolB = (ks * 16 + (lane >> 4) * 8) * 2;
            #pragma unroll
            for (int mi = 0; mi < 4; mi++) {
                uint32_t off = (arow + mi * 16) * ROWB + acolB;
                LDMX4(ah[mi], base + 0 * TILE_B + off);
                LDMX4(al[mi], base + 1 * TILE_B + off);
            }
            const int brow = wn0 + (lane & 7);
            const int bcolB = (ks * 16 + ((lane >> 3) & 1) * 8) * 2;
            #pragma unroll
            for (int ni = 0; ni < 4; ni++) {
                uint32_t off = (brow + ni * 8) * ROWB + bcolB;
                LDMX2(bh[ni], base + 2 * TILE_B + off);
                LDMX2(bl[ni], base + 3 * TILE_B + off);
            }
            #pragma unroll
            for (int mi = 0; mi < 4; mi++)
                #pragma unroll
                for (int ni = 0; ni < 4; ni++) {
                    MMA16816(acc[mi][ni], ah[mi], bh[ni]);
                    MMA16816(acc[mi][ni], ah[mi], bl[ni]);
                    MMA16816(acc[mi][ni], al[mi], bh[ni]);
                }
        }
        __syncthreads();
    }

    // epilogue straight from accumulators.
    // frag (mi,ni): lane holds C[r][c],C[r][c+1] and C[r+8][c],C[r+8][c+1],
    // r = lane>>2, c = 2*(lane&3)  (c even -> RoPE pair)
    const int r = lane >> 2;
    const int cc = (lane & 3) * 2;
    #pragma unroll
    for (int mi = 0; mi < 4; mi++) {
        #pragma unroll
        for (int ni = 0; ni < 4; ni++) {
            int mg = m0 + wm0 + mi * 16 + r;
            int ng = n0 + wn0 + ni * 8 + cc;
            #pragma unroll
            for (int half = 0; half < 2; half++) {
                int m = mg + half * 8;
                float e = acc[mi][ni][half * 2 + 0];
                float o = acc[mi][ni][half * 2 + 1];
                if (MODE == 0) {
                    float2 v = {e, o};
                    *(float2*)&out[(size_t)m * DMODEL + ng] = v;
                } else {
                    int h = ng >> 6, nh = ng & 63;
                    int b = m >> 11, s = m & (SEQ - 1);
                    float* dst = out + (((size_t)(b * NHEADS + h) * SEQ + s) << 6) + nh;
                    if (MODE == 1) {
                        float pos = (float)posarr[s];
                        float fr = exp2f(-LOG2_THETA * (float)(nh >> 1) * (1.0f / 32.0f));
                        float sn, cs;
                        sincosf(pos * fr, &sn, &cs);
                        float2 v = {e * cs - o * sn, e * sn + o * cs};
                        *(float2*)dst = v;
                    } else {
                        float2 v = {e, o};
                        *(float2*)dst = v;
                    }
                }
            }
        }
    }
}

// ---------------------------------------------------------------------------
// Causal flash attention, fp32 (unchanged; proven correct). Q/K/V [b*h, S, 64].
// ---------------------------------------------------------------------------
__global__ __launch_bounds__(64)
void attn_kernel(const float* __restrict__ Q, const float* __restrict__ K,
                 const float* __restrict__ V, float* __restrict__ out)
{
    __shared__ float Ks[64][64];
    __shared__ float Vs[64][64];

    const int bh = blockIdx.y;
    const int qb = blockIdx.x;
    const int t  = threadIdx.x;
    const int qi = qb * 64 + t;

    const float* Qb = Q + (size_t)bh * SEQ * HDIM;
    const float* Kb = K + (size_t)bh * SEQ * HDIM;
    const float* Vb = V + (size_t)bh * SEQ * HDIM;

    float q[64];
    {
        const float* qrow = Qb + (size_t)qi * HDIM;
        #pragma unroll
        for (int d4 = 0; d4 < 16; d4++) {
            float4 v = *(const float4*)(qrow + d4*4);
            q[d4*4+0] = v.x * 0.125f; q[d4*4+1] = v.y * 0.125f;
            q[d4*4+2] = v.z * 0.125f; q[d4*4+3] = v.w * 0.125f;
        }
    }

    float acc[64];
    #pragma unroll
    for (int d = 0; d < 64; d++) acc[d] = 0.f;
    float mmax = -INFINITY, l = 0.f;

    for (int kb = 0; kb <= qb; kb++) {
        #pragma unroll 4
        for (int p = 0; p < 64; p++) {
            Ks[p][t] = Kb[((size_t)(kb*64 + p)) * HDIM + t];
            Vs[p][t] = Vb[((size_t)(kb*64 + p)) * HDIM + t];
        }
        __syncthreads();

        const int jmax = (kb == qb) ? (t + 1) : 64;
        for (int j = 0; j < jmax; j++) {
            float s = 0.f;
            #pragma unroll
            for (int d4 = 0; d4 < 16; d4++) {
                float4 kk = *(const float4*)&Ks[j][d4*4];
                s += q[d4*4+0]*kk.x + q[d4*4+1]*kk.y
                   + q[d4*4+2]*kk.z + q[d4*4+3]*kk.w;
            }
            if (s > mmax) {
                float f = __expf(mmax - s);
                l *= f;
                #pragma unroll
                for (int d = 0; d < 64; d++) acc[d] *= f;
                mmax = s;
            }
            float p = __expf(s - mmax);
            l += p;
            #pragma unroll
            for (int d4 = 0; d4 < 16; d4++) {
                float4 vv = *(const float4*)&Vs[j][d4*4];
                acc[d4*4+0] += p * vv.x; acc[d4*4+1] += p * vv.y;
                acc[d4*4+2] += p * vv.z; acc[d4*4+3] += p * vv.w;
            }
        }
        __syncthreads();
    }

    const int b = bh / NHEADS;
    const int h = bh % NHEADS;
    float inv = 1.0f / l;
    float* o = out + ((size_t)(b * SEQ + qi)) * DMODEL + h * HDIM;
    #pragma unroll
    for (int d4 = 0; d4 < 16; d4++) {
        float4 v = make_float4(acc[d4*4+0]*inv, acc[d4*4+1]*inv,
                               acc[d4*4+2]*inv, acc[d4*4+3]*inv);
        *(float4*)(o + d4*4) = v;
    }
}

// ---------------------------------------------------------------------------
extern "C" void kernel_launch(void* const* d_in, const int* in_sizes, int n_in,
                              void* d_out, int out_size)
{
    const float* x   = (const float*)d_in[0];
    const float* Wq  = (const float*)d_in[1];
    const float* Wk  = (const float*)d_in[2];
    const float* Wv  = (const float*)d_in[3];
    const float* Wo  = (const float*)d_in[4];
    const int*   pos = (const int*)d_in[6];
    float* out       = (float*)d_out;

    float *gQ, *gK, *gV, *gA;
    __nv_bfloat16 *xh, *xl, *wh, *wl, *ah, *al;
    cudaGetSymbolAddress((void**)&gQ, g_Q);
    cudaGetSymbolAddress((void**)&gK, g_K);
    cudaGetSymbolAddress((void**)&gV, g_V);
    cudaGetSymbolAddress((void**)&gA, g_attn);
    cudaGetSymbolAddress((void**)&xh, g_xh);
    cudaGetSymbolAddress((void**)&xl, g_xl);
    cudaGetSymbolAddress((void**)&wh, g_wh);
    cudaGetSymbolAddress((void**)&wl, g_wl);
    cudaGetSymbolAddress((void**)&ah, g_ah);
    cudaGetSymbolAddress((void**)&al, g_al);

    cudaFuncSetAttribute(gemm_mma<0>, cudaFuncAttributeMaxDynamicSharedMemorySize, SMEM_TOTAL);
    cudaFuncSetAttribute(gemm_mma<1>, cudaFuncAttributeMaxDynamicSharedMemorySize, SMEM_TOTAL);
    cudaFuncSetAttribute(gemm_mma<2>, cudaFuncAttributeMaxDynamicSharedMemorySize, SMEM_TOTAL);

    const int NX4 = MTOT * DMODEL / 4;
    const int NW4 = DMODEL * DMODEL / 4;
    const size_t WSTRIDE = (size_t)DMODEL * DMODEL;

    split_f32<<<(NX4 + 255) / 256, 256>>>(x,  xh, xl, NX4);
    split_f32<<<(NW4 + 255) / 256, 256>>>(Wq, wh + 0*WSTRIDE, wl + 0*WSTRIDE, NW4);
    split_f32<<<(NW4 + 255) / 256, 256>>>(Wk, wh + 1*WSTRIDE, wl + 1*WSTRIDE, NW4);
    split_f32<<<(NW4 + 255) / 256, 256>>>(Wv, wh + 2*WSTRIDE, wl + 2*WSTRIDE, NW4);
    split_f32<<<(NW4 + 255) / 256, 256>>>(Wo, wh + 3*WSTRIDE, wl + 3*WSTRIDE, NW4);

    dim3 gg(DMODEL / BN, MTOT / BM);         // (8, 32) = 256 CTAs
    gemm_mma<1><<<gg, 256, SMEM_TOTAL>>>(xh, xl, wh + 0*WSTRIDE, wl + 0*WSTRIDE, gQ, pos);
    gemm_mma<1><<<gg, 256, SMEM_TOTAL>>>(xh, xl, wh + 1*WSTRIDE, wl + 1*WSTRIDE, gK, pos);
    gemm_mma<2><<<gg, 256, SMEM_TOTAL>>>(xh, xl, wh + 2*WSTRIDE, wl + 2*WSTRIDE, gV, nullptr);

    dim3 ga(SEQ / 64, BATCH * NHEADS);       // (32, 32)
    attn_kernel<<<ga, 64>>>(gQ, gK, gV, gA);

    split_f32<<<(NX4 + 255) / 256, 256>>>(gA, ah, al, NX4);
    gemm_mma<0><<<gg, 256, SMEM_TOTAL>>>(ah, al, wh + 3*WSTRIDE, wl + 3*WSTRIDE, out, nullptr);
}

// round 6
// speedup vs baseline: 3.4642x; 2.2071x over previous
#include <cuda_runtime.h>
#include <cuda_bf16.h>
#include <math.h>
#include <stdint.h>

#define BATCH   2
#define SEQ     2048
#define DMODEL  1024
#define NHEADS  16
#define HDIM    64
#define MTOT    (BATCH*SEQ)           // 4096
#define LOG2_THETA 13.28771238f       // log2(10000)
#define C_SCALE 0.18033688f           // log2(e)/8  (softmax scale folded into exp2)

// ---- HMMA GEMM tiling ----
#define BM 128
#define BN 128
#define BKE 64
#define PITCHE 72
#define ROWB (PITCHE*2)                // 144 bytes per row
#define TILE_B (128*ROWB)              // 18432
#define STAGE_B (4*TILE_B)             // 73728
#define SMEM_TOTAL (2*STAGE_B)         // 147456

// ---- attention tiling ----
#define ATILE_B (64*144)               // one 64x64 bf16 tile, 144B pitch = 9216
#define ASTAGE  (4*ATILE_B)            // Kh,Kl,Vh,Vl = 36864
#define ASMEM   (2*ASTAGE)             // 73728

// ---- scratch (__device__ globals; no allocs allowed) ----
__device__ __nv_bfloat16 g_Qh[BATCH*NHEADS*SEQ*HDIM], g_Ql[BATCH*NHEADS*SEQ*HDIM];
__device__ __nv_bfloat16 g_Kh[BATCH*NHEADS*SEQ*HDIM], g_Kl[BATCH*NHEADS*SEQ*HDIM];
__device__ __nv_bfloat16 g_Vh[BATCH*NHEADS*SEQ*HDIM], g_Vl[BATCH*NHEADS*SEQ*HDIM];
__device__ __nv_bfloat16 g_xh[MTOT*DMODEL], g_xl[MTOT*DMODEL];
__device__ __nv_bfloat16 g_wh[4][DMODEL*DMODEL], g_wl[4][DMODEL*DMODEL];
__device__ __nv_bfloat16 g_ah[MTOT*DMODEL], g_al[MTOT*DMODEL];

// ---------------------------------------------------------------------------
// PTX helpers (sm_80-era only; tcgen05 rejected by this toolchain's ptxas)
// ---------------------------------------------------------------------------
__device__ __forceinline__ uint32_t smem_u32(const void* p) {
    uint32_t a;
    asm("{ .reg .u64 t; cvta.to.shared.u64 t, %1; cvt.u32.u64 %0, t; }" : "=r"(a) : "l"(p));
    return a;
}
#define CP16(s, g)  asm volatile("cp.async.cg.shared.global [%0], [%1], 16;" :: "r"(s), "l"(g))
#define CPCOMMIT()  asm volatile("cp.async.commit_group;" ::: "memory")
#define CPWAIT0()   asm volatile("cp.async.wait_group 0;" ::: "memory")
#define CPWAIT1()   asm volatile("cp.async.wait_group 1;" ::: "memory")

#define LDMX4(r, a) asm volatile("ldmatrix.sync.aligned.m8n8.x4.shared.b16 {%0,%1,%2,%3}, [%4];" \
    : "=r"((r)[0]), "=r"((r)[1]), "=r"((r)[2]), "=r"((r)[3]) : "r"(a))
#define LDMX2(r, a) asm volatile("ldmatrix.sync.aligned.m8n8.x2.shared.b16 {%0,%1}, [%2];" \
    : "=r"((r)[0]), "=r"((r)[1]) : "r"(a))
#define LDMX2T(r, a) asm volatile("ldmatrix.sync.aligned.m8n8.x2.trans.shared.b16 {%0,%1}, [%2];" \
    : "=r"((r)[0]), "=r"((r)[1]) : "r"(a))

#define MMA16816(c, a, b) asm volatile( \
    "mma.sync.aligned.m16n8k16.row.col.f32.bf16.bf16.f32 " \
    "{%0,%1,%2,%3},{%4,%5,%6,%7},{%8,%9},{%0,%1,%2,%3};" \
    : "+f"((c)[0]), "+f"((c)[1]), "+f"((c)[2]), "+f"((c)[3]) \
    : "r"((a)[0]), "r"((a)[1]), "r"((a)[2]), "r"((a)[3]), "r"((b)[0]), "r"((b)[1]))

__device__ __forceinline__ float ex2(float x) {
    float r; asm("ex2.approx.ftz.f32 %0, %1;" : "=f"(r) : "f"(x)); return r;
}
__device__ __forceinline__ void split2_store(float v0, float v1,
                                             __nv_bfloat16* ph, __nv_bfloat16* pl) {
    __nv_bfloat162 hv, lv;
    hv.x = __float2bfloat16(v0); hv.y = __float2bfloat16(v1);
    lv.x = __float2bfloat16(v0 - __bfloat162float(hv.x));
    lv.y = __float2bfloat16(v1 - __bfloat162float(hv.y));
    *(__nv_bfloat162*)ph = hv;
    *(__nv_bfloat162*)pl = lv;
}

// ---------------------------------------------------------------------------
// fp32 -> (hi,lo) bf16 split conversion
// ---------------------------------------------------------------------------
__global__ __launch_bounds__(256)
void split_f32(const float* __restrict__ in, __nv_bfloat16* __restrict__ hi,
               __nv_bfloat16* __restrict__ lo, int n4)
{
    int i = blockIdx.x * 256 + threadIdx.x;
    if (i >= n4) return;
    float4 v = ((const float4*)in)[i];
    __nv_bfloat16 h0 = __float2bfloat16(v.x), h1 = __float2bfloat16(v.y);
    __nv_bfloat16 h2 = __float2bfloat16(v.z), h3 = __float2bfloat16(v.w);
    __nv_bfloat16 l0 = __float2bfloat16(v.x - __bfloat162float(h0));
    __nv_bfloat16 l1 = __float2bfloat16(v.y - __bfloat162float(h1));
    __nv_bfloat16 l2 = __float2bfloat16(v.z - __bfloat162float(h2));
    __nv_bfloat16 l3 = __float2bfloat16(v.w - __bfloat162float(h3));
    __nv_bfloat162 hA = {h0, h1}, hB = {h2, h3}, lA = {l0, l1}, lB = {l2, l3};
    uint2 uh, ul;
    uh.x = *(uint32_t*)&hA; uh.y = *(uint32_t*)&hB;
    ul.x = *(uint32_t*)&lA; ul.y = *(uint32_t*)&lB;
    ((uint2*)hi)[i] = uh;
    ((uint2*)lo)[i] = ul;
}

// ---------------------------------------------------------------------------
// split-bf16 HMMA GEMM: C = A @ W^T (as R3, validated).
// MODE 0: fp32 [M,1024] to outF
// MODE 1: RoPE + head-split, split-bf16 to outH/outL  [b*h, s, 64]
// MODE 2: head-split, split-bf16 to outH/outL
// ---------------------------------------------------------------------------
template<int MODE>
__global__ __launch_bounds__(256)
void gemm_mma(const __nv_bfloat16* __restrict__ Ahi, const __nv_bfloat16* __restrict__ Alo,
              const __nv_bfloat16* __restrict__ Bhi, const __nv_bfloat16* __restrict__ Blo,
              float* __restrict__ outF, __nv_bfloat16* __restrict__ outH,
              __nv_bfloat16* __restrict__ outL, const int* __restrict__ posarr)
{
    extern __shared__ char smem[];
    const uint32_t sb = smem_u32(smem);
    const int tid  = threadIdx.x;
    const int warp = tid >> 5;
    const int lane = tid & 31;
    const int m0 = blockIdx.y * BM;
    const int n0 = blockIdx.x * BN;
    const int wm0 = (warp >> 2) * 64;
    const int wn0 = (warp & 3) * 32;

    float acc[4][4][4];
    #pragma unroll
    for (int i = 0; i < 4; i++)
        #pragma unroll
        for (int j = 0; j < 4; j++)
            #pragma unroll
            for (int k = 0; k < 4; k++) acc[i][j][k] = 0.f;

    const __nv_bfloat16* srcs[4] = {
        Ahi + (size_t)m0 * DMODEL, Alo + (size_t)m0 * DMODEL,
        Bhi + (size_t)n0 * DMODEL, Blo + (size_t)n0 * DMODEL
    };

    auto issue = [&](int buf, int chunk) {
        const int kof = chunk * BKE;
        #pragma unroll
        for (int t = 0; t < 16; t++) {
            int j = t * 256 + tid;
            int tile = j >> 10;
            int v = j & 1023;
            int row = v >> 3, c = v & 7;
            const __nv_bfloat16* g = srcs[tile] + (size_t)row * DMODEL + kof + c * 8;
            uint32_t s = sb + buf * STAGE_B + tile * TILE_B + row * ROWB + c * 16;
            CP16(s, g);
        }
        CPCOMMIT();
    };

    issue(0, 0);

    for (int i = 0; i < 16; i++) {
        if (i < 15) { issue((i + 1) & 1, i + 1); CPWAIT1(); }
        else        { CPWAIT0(); }
        __syncthreads();

        const uint32_t base = sb + (i & 1) * STAGE_B;
        #pragma unroll
        for (int ks = 0; ks < 4; ks++) {
            uint32_t ah[4][4], al[4][4], bh[4][2], bl[4][2];
            const int arow = wm0 + (lane & 15);
            const int acolB = (ks * 16 + (lane >> 4) * 8) * 2;
            #pragma unroll
            for (int mi = 0; mi < 4; mi++) {
                uint32_t off = (arow + mi * 16) * ROWB + acolB;
                LDMX4(ah[mi], base + 0 * TILE_B + off);
                LDMX4(al[mi], base + 1 * TILE_B + off);
            }
            const int brow = wn0 + (lane & 7);
            const int bcolB = (ks * 16 + ((lane >> 3) & 1) * 8) * 2;
            #pragma unroll
            for (int ni = 0; ni < 4; ni++) {
                uint32_t off = (brow + ni * 8) * ROWB + bcolB;
                LDMX2(bh[ni], base + 2 * TILE_B + off);
                LDMX2(bl[ni], base + 3 * TILE_B + off);
            }
            #pragma unroll
            for (int mi = 0; mi < 4; mi++)
                #pragma unroll
                for (int ni = 0; ni < 4; ni++) {
                    MMA16816(acc[mi][ni], ah[mi], bh[ni]);
                    MMA16816(acc[mi][ni], ah[mi], bl[ni]);
                    MMA16816(acc[mi][ni], al[mi], bh[ni]);
                }
        }
        __syncthreads();
    }

    const int r = lane >> 2;
    const int cc = (lane & 3) * 2;
    #pragma unroll
    for (int mi = 0; mi < 4; mi++) {
        #pragma unroll
        for (int ni = 0; ni < 4; ni++) {
            int mg = m0 + wm0 + mi * 16 + r;
            int ng = n0 + wn0 + ni * 8 + cc;
            #pragma unroll
            for (int half = 0; half < 2; half++) {
                int m = mg + half * 8;
                float e = acc[mi][ni][half * 2 + 0];
                float o = acc[mi][ni][half * 2 + 1];
                if (MODE == 0) {
                    float2 v = {e, o};
                    *(float2*)&outF[(size_t)m * DMODEL + ng] = v;
                } else {
                    int h = ng >> 6, nh = ng & 63;
                    int b = m >> 11, s = m & (SEQ - 1);
                    size_t off = (((size_t)(b * NHEADS + h) * SEQ + s) << 6) + nh;
                    if (MODE == 1) {
                        float pos = (float)posarr[s];
                        float fr = exp2f(-LOG2_THETA * (float)(nh >> 1) * (1.0f / 32.0f));
                        float sn, cs;
                        sincosf(pos * fr, &sn, &cs);
                        float re = e * cs - o * sn;
                        float ro = e * sn + o * cs;
                        split2_store(re, ro, outH + off, outL + off);
                    } else {
                        split2_store(e, o, outH + off, outL + off);
                    }
                }
            }
        }
    }
}

// ---------------------------------------------------------------------------
// HMMA flash attention, split-bf16, causal.
// CTA: 128 q rows, 8 warps (16 rows each); 64-key blocks; cp.async dbl buffer.
// Inputs [b*h, S, 64] split bf16; output split bf16 [b, s, 1024].
// ---------------------------------------------------------------------------
__global__ __launch_bounds__(256)
void attn_mma(const __nv_bfloat16* __restrict__ Qh, const __nv_bfloat16* __restrict__ Ql,
              const __nv_bfloat16* __restrict__ Kh, const __nv_bfloat16* __restrict__ Kl,
              const __nv_bfloat16* __restrict__ Vh, const __nv_bfloat16* __restrict__ Vl,
              __nv_bfloat16* __restrict__ outH, __nv_bfloat16* __restrict__ outL)
{
    extern __shared__ char smem[];
    const uint32_t sb = smem_u32(smem);
    const int tid = threadIdx.x, warp = tid >> 5, lane = tid & 31;
    const int g = lane >> 2, t = lane & 3;
    const int qb = (int)gridDim.x - 1 - (int)blockIdx.x;   // heavy CTAs first
    const int bh = blockIdx.y;
    const size_t bhoff = (size_t)bh * SEQ * HDIM;
    const int qrow0 = qb * 128 + warp * 16;

    // Q fragments (direct LDG, once)
    uint32_t qa_h[4][4], qa_l[4][4];
    {
        const __nv_bfloat16* Qbh = Qh + bhoff + (size_t)qrow0 * 64;
        const __nv_bfloat16* Qbl = Ql + bhoff + (size_t)qrow0 * 64;
        #pragma unroll
        for (int u = 0; u < 4; u++) {
            int c0 = u * 16 + 2 * t;
            qa_h[u][0] = *(const uint32_t*)(Qbh + (g    ) * 64 + c0);
            qa_h[u][1] = *(const uint32_t*)(Qbh + (g + 8) * 64 + c0);
            qa_h[u][2] = *(const uint32_t*)(Qbh + (g    ) * 64 + c0 + 8);
            qa_h[u][3] = *(const uint32_t*)(Qbh + (g + 8) * 64 + c0 + 8);
            qa_l[u][0] = *(const uint32_t*)(Qbl + (g    ) * 64 + c0);
            qa_l[u][1] = *(const uint32_t*)(Qbl + (g + 8) * 64 + c0);
            qa_l[u][2] = *(const uint32_t*)(Qbl + (g    ) * 64 + c0 + 8);
            qa_l[u][3] = *(const uint32_t*)(Qbl + (g + 8) * 64 + c0 + 8);
        }
    }

    float accO[8][4];
    #pragma unroll
    for (int i = 0; i < 8; i++)
        #pragma unroll
        for (int j = 0; j < 4; j++) accO[i][j] = 0.f;
    float m0 = -1e38f, m1 = -1e38f, l0 = 0.f, l1 = 0.f;

    const int nkb = 2 * qb + 2;
    const __nv_bfloat16* srcs[4] = {Kh + bhoff, Kl + bhoff, Vh + bhoff, Vl + bhoff};

    auto issue = [&](int buf, int kb) {
        #pragma unroll
        for (int it = 0; it < 8; it++) {
            int j = it * 256 + tid;
            int tile = j >> 9, v = j & 511, row = v >> 3, c = v & 7;
            const __nv_bfloat16* gp = srcs[tile] + (((size_t)(kb * 64 + row)) << 6) + c * 8;
            uint32_t sa = sb + buf * ASTAGE + tile * ATILE_B + row * 144 + c * 16;
            CP16(sa, gp);
        }
        CPCOMMIT();
    };

    issue(0, 0);

    for (int kb = 0; kb < nkb; kb++) {
        if (kb + 1 < nkb) { issue((kb + 1) & 1, kb + 1); CPWAIT1(); }
        else              { CPWAIT0(); }
        __syncthreads();

        const uint32_t base = sb + (kb & 1) * ASTAGE;

        // ---- S = Q K^T (3-term split), fp32 accum ----
        float S[8][4];
        #pragma unroll
        for (int i = 0; i < 8; i++)
            #pragma unroll
            for (int j = 0; j < 4; j++) S[i][j] = 0.f;

        #pragma unroll
        for (int nt = 0; nt < 8; nt++) {
            #pragma unroll
            for (int u = 0; u < 4; u++) {
                uint32_t off = (nt * 8 + (lane & 7)) * 144 + (u * 16 + ((lane >> 3) & 1) * 8) * 2;
                uint32_t kh2[2], kl2[2];
                LDMX2(kh2, base + 0 * ATILE_B + off);
                LDMX2(kl2, base + 1 * ATILE_B + off);
                MMA16816(S[nt], qa_h[u], kh2);
                MMA16816(S[nt], qa_h[u], kl2);
                MMA16816(S[nt], qa_l[u], kh2);
            }
        }

        // ---- causal mask (diagonal blocks only) ----
        if (kb * 64 + 63 > qrow0) {
            #pragma unroll
            for (int nt = 0; nt < 8; nt++) {
                int key = kb * 64 + nt * 8 + 2 * t;
                int r0 = qrow0 + g, r1 = r0 + 8;
                if (key     > r0) S[nt][0] = -1e30f;
                if (key + 1 > r0) S[nt][1] = -1e30f;
                if (key     > r1) S[nt][2] = -1e30f;
                if (key + 1 > r1) S[nt][3] = -1e30f;
            }
        }

        // ---- online softmax ----
        float mx0 = -1e38f, mx1 = -1e38f;
        #pragma unroll
        for (int nt = 0; nt < 8; nt++) {
            mx0 = fmaxf(mx0, fmaxf(S[nt][0], S[nt][1]));
            mx1 = fmaxf(mx1, fmaxf(S[nt][2], S[nt][3]));
        }
        mx0 = fmaxf(mx0, __shfl_xor_sync(0xffffffffu, mx0, 1));
        mx0 = fmaxf(mx0, __shfl_xor_sync(0xffffffffu, mx0, 2));
        mx1 = fmaxf(mx1, __shfl_xor_sync(0xffffffffu, mx1, 1));
        mx1 = fmaxf(mx1, __shfl_xor_sync(0xffffffffu, mx1, 2));
        float mN0 = fmaxf(m0, mx0), mN1 = fmaxf(m1, mx1);
        float sc0 = ex2((m0 - mN0) * C_SCALE);
        float sc1 = ex2((m1 - mN1) * C_SCALE);
        m0 = mN0; m1 = mN1;
        l0 *= sc0; l1 *= sc1;
        #pragma unroll
        for (int nt = 0; nt < 8; nt++) {
            accO[nt][0] *= sc0; accO[nt][1] *= sc0;
            accO[nt][2] *= sc1; accO[nt][3] *= sc1;
        }

        // ---- p = exp2((s-m)*C), accumulate l, split-pack to bf16x2 ----
        uint32_t Ph[8][2], Pl[8][2];
        #pragma unroll
        for (int nt = 0; nt < 8; nt++) {
            float p0 = ex2((S[nt][0] - m0) * C_SCALE);
            float p1 = ex2((S[nt][1] - m0) * C_SCALE);
            float p2 = ex2((S[nt][2] - m1) * C_SCALE);
            float p3 = ex2((S[nt][3] - m1) * C_SCALE);
            l0 += p0 + p1;
            l1 += p2 + p3;
            __nv_bfloat162 h01, h23, r01, r23;
            h01.x = __float2bfloat16(p0); h01.y = __float2bfloat16(p1);
            h23.x = __float2bfloat16(p2); h23.y = __float2bfloat16(p3);
            r01.x = __float2bfloat16(p0 - __bfloat162float(h01.x));
            r01.y = __float2bfloat16(p1 - __bfloat162float(h01.y));
            r23.x = __float2bfloat16(p2 - __bfloat162float(h23.x));
            r23.y = __float2bfloat16(p3 - __bfloat162float(h23.y));
            Ph[nt][0] = *(uint32_t*)&h01; Ph[nt][1] = *(uint32_t*)&h23;
            Pl[nt][0] = *(uint32_t*)&r01; Pl[nt][1] = *(uint32_t*)&r23;
        }

        // ---- O += P V (3-term split) ----
        #pragma unroll
        for (int u = 0; u < 4; u++) {
            uint32_t aph[4] = {Ph[2*u][0], Ph[2*u][1], Ph[2*u+1][0], Ph[2*u+1][1]};
            uint32_t apl[4] = {Pl[2*u][0], Pl[2*u][1], Pl[2*u+1][0], Pl[2*u+1][1]};
            #pragma unroll
            for (int nt = 0; nt < 8; nt++) {
                uint32_t voff = (u * 16 + (lane & 15)) * 144 + nt * 8 * 2;
                uint32_t vh2[2], vl2[2];
                LDMX2T(vh2, base + 2 * ATILE_B + voff);
                LDMX2T(vl2, base + 3 * ATILE_B + voff);
                MMA16816(accO[nt], aph, vh2);
                MMA16816(accO[nt], aph, vl2);
                MMA16816(accO[nt], apl, vh2);
            }
        }
        __syncthreads();
    }

    // ---- finalize: l row-sum, normalize, split-store to [b, s, 1024] ----
    l0 += __shfl_xor_sync(0xffffffffu, l0, 1);
    l0 += __shfl_xor_sync(0xffffffffu, l0, 2);
    l1 += __shfl_xor_sync(0xffffffffu, l1, 1);
    l1 += __shfl_xor_sync(0xffffffffu, l1, 2);
    float inv0 = 1.0f / l0, inv1 = 1.0f / l1;

    const int b = bh >> 4, h = bh & 15;
    const int s0 = qrow0 + g, s1 = s0 + 8;
    #pragma unroll
    for (int nt = 0; nt < 8; nt++) {
        int col = h * 64 + nt * 8 + 2 * t;
        size_t i0 = ((size_t)(b * SEQ + s0)) * DMODEL + col;
        size_t i1 = ((size_t)(b * SEQ + s1)) * DMODEL + col;
        split2_store(accO[nt][0] * inv0, accO[nt][1] * inv0, outH + i0, outL + i0);
        split2_store(accO[nt][2] * inv1, accO[nt][3] * inv1, outH + i1, outL + i1);
    }
}

// ---------------------------------------------------------------------------
extern "C" void kernel_launch(void* const* d_in, const int* in_sizes, int n_in,
                              void* d_out, int out_size)
{
    const float* x   = (const float*)d_in[0];
    const float* Wq  = (const float*)d_in[1];
    const float* Wk  = (const float*)d_in[2];
    const float* Wv  = (const float*)d_in[3];
    const float* Wo  = (const float*)d_in[4];
    const int*   pos = (const int*)d_in[6];
    float* out       = (float*)d_out;

    __nv_bfloat16 *qh, *ql, *kh, *kl, *vh, *vl, *xh, *xl, *wh, *wl, *ah, *al;
    cudaGetSymbolAddress((void**)&qh, g_Qh); cudaGetSymbolAddress((void**)&ql, g_Ql);
    cudaGetSymbolAddress((void**)&kh, g_Kh); cudaGetSymbolAddress((void**)&kl, g_Kl);
    cudaGetSymbolAddress((void**)&vh, g_Vh); cudaGetSymbolAddress((void**)&vl, g_Vl);
    cudaGetSymbolAddress((void**)&xh, g_xh); cudaGetSymbolAddress((void**)&xl, g_xl);
    cudaGetSymbolAddress((void**)&wh, g_wh); cudaGetSymbolAddress((void**)&wl, g_wl);
    cudaGetSymbolAddress((void**)&ah, g_ah); cudaGetSymbolAddress((void**)&al, g_al);

    cudaFuncSetAttribute(gemm_mma<0>, cudaFuncAttributeMaxDynamicSharedMemorySize, SMEM_TOTAL);
    cudaFuncSetAttribute(gemm_mma<1>, cudaFuncAttributeMaxDynamicSharedMemorySize, SMEM_TOTAL);
    cudaFuncSetAttribute(gemm_mma<2>, cudaFuncAttributeMaxDynamicSharedMemorySize, SMEM_TOTAL);
    cudaFuncSetAttribute(attn_mma,    cudaFuncAttributeMaxDynamicSharedMemorySize, ASMEM);

    const int NX4 = MTOT * DMODEL / 4;
    const int NW4 = DMODEL * DMODEL / 4;
    const size_t WS = (size_t)DMODEL * DMODEL;

    split_f32<<<(NX4 + 255) / 256, 256>>>(x,  xh, xl, NX4);
    split_f32<<<(NW4 + 255) / 256, 256>>>(Wq, wh + 0*WS, wl + 0*WS, NW4);
    split_f32<<<(NW4 + 255) / 256, 256>>>(Wk, wh + 1*WS, wl + 1*WS, NW4);
    split_f32<<<(NW4 + 255) / 256, 256>>>(Wv, wh + 2*WS, wl + 2*WS, NW4);
    split_f32<<<(NW4 + 255) / 256, 256>>>(Wo, wh + 3*WS, wl + 3*WS, NW4);

    dim3 gg(DMODEL / BN, MTOT / BM);         // (8, 32)
    gemm_mma<1><<<gg, 256, SMEM_TOTAL>>>(xh, xl, wh + 0*WS, wl + 0*WS, nullptr, qh, ql, pos);
    gemm_mma<1><<<gg, 256, SMEM_TOTAL>>>(xh, xl, wh + 1*WS, wl + 1*WS, nullptr, kh, kl, pos);
    gemm_mma<2><<<gg, 256, SMEM_TOTAL>>>(xh, xl, wh + 2*WS, wl + 2*WS, nullptr, vh, vl, nullptr);

    dim3 ga(SEQ / 128, BATCH * NHEADS);      // (16, 32) = 512 CTAs
    attn_mma<<<ga, 256, ASMEM>>>(qh, ql, kh, kl, vh, vl, ah, al);

    gemm_mma<0><<<gg, 256, SMEM_TOTAL>>>(ah, al, wh + 3*WS, wl + 3*WS, out, nullptr, nullptr, nullptr);
}

// round 9
// speedup vs baseline: 4.6679x; 1.3475x over previous
#include <cuda_runtime.h>
#include <cuda_fp16.h>
#include <math.h>
#include <stdint.h>

#define BATCH   2
#define SEQ     2048
#define DMODEL  1024
#define NHEADS  16
#define HDIM    64
#define MTOT    (BATCH*SEQ)           // 4096
#define LOG2_THETA 13.28771238f       // log2(10000)
#define C_SCALE 0.18033688f           // log2(e)/8

// ---- GEMM tiling: A plain fp16, B split fp16 (hi/lo) -> 3 tiles/stage ----
#define BM 128
#define BN 128
#define BKE 64
#define ROWB 144                       // 72 elems * 2B, padded pitch
#define TILE_B (128*ROWB)              // 18432
#define STAGE3 (3*TILE_B)              // 55296
#define SMEM_G (2*STAGE3)              // 110592

// ---- attention tiling (Kh,Kl,Vh,Vl tiles) ----
#define ATILE_B (64*144)               // 9216
#define ASTAGE  (4*ATILE_B)            // 36864
#define ASMEM   (2*ASTAGE)             // 73728

// ---- scratch ----
__device__ half g_x16[MTOT*DMODEL];
__device__ half g_wh[4][DMODEL*DMODEL], g_wl[4][DMODEL*DMODEL];
__device__ half g_Qh[BATCH*NHEADS*SEQ*HDIM], g_Ql[BATCH*NHEADS*SEQ*HDIM];
__device__ half g_Kh[BATCH*NHEADS*SEQ*HDIM], g_Kl[BATCH*NHEADS*SEQ*HDIM];
__device__ half g_Vh[BATCH*NHEADS*SEQ*HDIM], g_Vl[BATCH*NHEADS*SEQ*HDIM];
__device__ half g_a16[MTOT*DMODEL];
__device__ float2 g_rope[SEQ*32];      // (cos,sin) per (s, d/2)

// ---------------------------------------------------------------------------
// PTX helpers (sm_80-era; tcgen05 rejected by this toolchain's ptxas)
// ---------------------------------------------------------------------------
__device__ __forceinline__ uint32_t smem_u32(const void* p) {
    uint32_t a;
    asm("{ .reg .u64 t; cvta.to.shared.u64 t, %1; cvt.u32.u64 %0, t; }" : "=r"(a) : "l"(p));
    return a;
}
#define CP16(s, g)  asm volatile("cp.async.cg.shared.global [%0], [%1], 16;" :: "r"(s), "l"(g))
#define CPCOMMIT()  asm volatile("cp.async.commit_group;" ::: "memory")
#define CPWAIT0()   asm volatile("cp.async.wait_group 0;" ::: "memory")
#define CPWAIT1()   asm volatile("cp.async.wait_group 1;" ::: "memory")

#define LDMX4(r, a) asm volatile("ldmatrix.sync.aligned.m8n8.x4.shared.b16 {%0,%1,%2,%3}, [%4];" \
    : "=r"((r)[0]), "=r"((r)[1]), "=r"((r)[2]), "=r"((r)[3]) : "r"(a))
#define LDMX2(r, a) asm volatile("ldmatrix.sync.aligned.m8n8.x2.shared.b16 {%0,%1}, [%2];" \
    : "=r"((r)[0]), "=r"((r)[1]) : "r"(a))
#define LDMX2T(r, a) asm volatile("ldmatrix.sync.aligned.m8n8.x2.trans.shared.b16 {%0,%1}, [%2];" \
    : "=r"((r)[0]), "=r"((r)[1]) : "r"(a))

#define MMA16816(c, a, b) asm volatile( \
    "mma.sync.aligned.m16n8k16.row.col.f32.f16.f16.f32 " \
    "{%0,%1,%2,%3},{%4,%5,%6,%7},{%8,%9},{%0,%1,%2,%3};" \
    : "+f"((c)[0]), "+f"((c)[1]), "+f"((c)[2]), "+f"((c)[3]) \
    : "r"((a)[0]), "r"((a)[1]), "r"((a)[2]), "r"((a)[3]), "r"((b)[0]), "r"((b)[1]))

__device__ __forceinline__ float ex2(float x) {
    float r; asm("ex2.approx.ftz.f32 %0, %1;" : "=f"(r) : "f"(x)); return r;
}
__device__ __forceinline__ void split2h(float v0, float v1, half* ph, half* pl) {
    half h0 = __float2half_rn(v0), h1 = __float2half_rn(v1);
    half l0 = __float2half_rn(v0 - __half2float(h0));
    half l1 = __float2half_rn(v1 - __half2float(h1));
    half2 hv = {h0, h1}, lv = {l0, l1};
    *(half2*)ph = hv;
    *(half2*)pl = lv;
}

// ---------------------------------------------------------------------------
// conversions
// ---------------------------------------------------------------------------
__global__ __launch_bounds__(256)
void conv_f16(const float* __restrict__ in, half* __restrict__ out, int n4)
{
    int i = blockIdx.x * 256 + threadIdx.x;
    if (i >= n4) return;
    float4 v = ((const float4*)in)[i];
    half2 a = __floats2half2_rn(v.x, v.y);
    half2 b = __floats2half2_rn(v.z, v.w);
    uint2 u;
    u.x = *(uint32_t*)&a; u.y = *(uint32_t*)&b;
    ((uint2*)out)[i] = u;
}

__global__ __launch_bounds__(256)
void split_w(const float* __restrict__ w0, const float* __restrict__ w1,
             const float* __restrict__ w2, const float* __restrict__ w3,
             half* __restrict__ hi, half* __restrict__ lo, int n4)
{
    int z = blockIdx.z;
    const float* w = (z == 0) ? w0 : (z == 1) ? w1 : (z == 2) ? w2 : w3;
    int i = blockIdx.x * 256 + threadIdx.x;
    if (i >= n4) return;
    float4 v = ((const float4*)w)[i];
    size_t base = (size_t)z * DMODEL * DMODEL / 4;
    half h0 = __float2half_rn(v.x), h1 = __float2half_rn(v.y);
    half h2 = __float2half_rn(v.z), h3 = __float2half_rn(v.w);
    half2 hA = {h0, h1}, hB = {h2, h3};
    half2 lA = {__float2half_rn(v.x - __half2float(h0)), __float2half_rn(v.y - __half2float(h1))};
    half2 lB = {__float2half_rn(v.z - __half2float(h2)), __float2half_rn(v.w - __half2float(h3))};
    uint2 uh, ul;
    uh.x = *(uint32_t*)&hA; uh.y = *(uint32_t*)&hB;
    ul.x = *(uint32_t*)&lA; ul.y = *(uint32_t*)&lB;
    ((uint2*)hi)[base + i] = uh;
    ((uint2*)lo)[base + i] = ul;
}

__global__ __launch_bounds__(256)
void rope_tab(const int* __restrict__ posarr, float2* __restrict__ tab)
{
    int i = blockIdx.x * 256 + threadIdx.x;   // SEQ*32
    int s = i >> 5, f = i & 31;
    float pos = (float)posarr[s];
    float fr = exp2f(-LOG2_THETA * (float)f * (1.0f / 32.0f));
    float sn, cs;
    sincosf(pos * fr, &sn, &cs);
    tab[i] = make_float2(cs, sn);
}

// ---------------------------------------------------------------------------
// 2-product fp16 HMMA GEMM: C = A @ W^T;  A plain fp16, W split hi/lo fp16.
// QKV=1: fused Q/K/V via blockIdx.z (RoPE for z<2, split-fp16 head-split out)
// QKV=0: O projection, fp32 output [M, 1024]
// ---------------------------------------------------------------------------
template<int QKV>
__global__ __launch_bounds__(256)
void gemm2(const half* __restrict__ A, const half* __restrict__ Wh0,
           const half* __restrict__ Wl0, float* __restrict__ outF,
           half* __restrict__ qh, half* __restrict__ ql,
           half* __restrict__ kh, half* __restrict__ kl,
           half* __restrict__ vh, half* __restrict__ vl,
           const float2* __restrict__ rope)
{
    extern __shared__ char smem[];
    const uint32_t sb = smem_u32(smem);
    const int tid  = threadIdx.x;
    const int warp = tid >> 5;
    const int lane = tid & 31;
    const int m0 = blockIdx.y * BM;
    const int n0 = blockIdx.x * BN;
    const int z  = QKV ? blockIdx.z : 0;
    const int wm0 = (warp >> 2) * 64;
    const int wn0 = (warp & 3) * 32;

    float acc[4][4][4];
    #pragma unroll
    for (int i = 0; i < 4; i++)
        #pragma unroll
        for (int j = 0; j < 4; j++)
            #pragma unroll
            for (int k = 0; k < 4; k++) acc[i][j][k] = 0.f;

    const size_t WS = (size_t)DMODEL * DMODEL;
    const half* srcs[3] = {
        A + (size_t)m0 * DMODEL,
        Wh0 + (size_t)z * WS + (size_t)n0 * DMODEL,
        Wl0 + (size_t)z * WS + (size_t)n0 * DMODEL
    };

    // stage = 3 tiles x 128 rows x 64 elems = 3072 x 16B vectors, 12/thread
    auto issue = [&](int buf, int chunk) {
        const int kof = chunk * BKE;
        #pragma unroll
        for (int t = 0; t < 12; t++) {
            int j = t * 256 + tid;
            int tile = j >> 10;
            int v = j & 1023;
            int row = v >> 3, c = v & 7;
            const half* g = srcs[tile] + (size_t)row * DMODEL + kof + c * 8;
            uint32_t s = sb + buf * STAGE3 + tile * TILE_B + row * ROWB + c * 16;
            CP16(s, g);
        }
        CPCOMMIT();
    };

    issue(0, 0);

    for (int i = 0; i < 16; i++) {
        if (i < 15) { issue((i + 1) & 1, i + 1); CPWAIT1(); }
        else        { CPWAIT0(); }
        __syncthreads();

        const uint32_t base = sb + (i & 1) * STAGE3;
        #pragma unroll
        for (int ks = 0; ks < 4; ks++) {
            uint32_t af[4][4], bh[4][2], bl[4][2];
            const int arow = wm0 + (lane & 15);
            const int acolB = (ks * 16 + (lane >> 4) * 8) * 2;
            #pragma unroll
            for (int mi = 0; mi < 4; mi++)
                LDMX4(af[mi], base + (arow + mi * 16) * ROWB + acolB);
            const int brow = wn0 + (lane & 7);
            const int bcolB = (ks * 16 + ((lane >> 3) & 1) * 8) * 2;
            #pragma unroll
            for (int ni = 0; ni < 4; ni++) {
                uint32_t off = (brow + ni * 8) * ROWB + bcolB;
                LDMX2(bh[ni], base + 1 * TILE_B + off);
                LDMX2(bl[ni], base + 2 * TILE_B + off);
            }
            #pragma unroll
            for (int mi = 0; mi < 4; mi++)
                #pragma unroll
                for (int ni = 0; ni < 4; ni++) {
                    MMA16816(acc[mi][ni], af[mi], bh[ni]);
                    MMA16816(acc[mi][ni], af[mi], bl[ni]);
                }
        }
        __syncthreads();
    }

    const int r = lane >> 2;
    const int cc = (lane & 3) * 2;
    half* oH = (z == 0) ? qh : (z == 1) ? kh : vh;
    half* oL = (z == 0) ? ql : (z == 1) ? kl : vl;
    #pragma unroll
    for (int mi = 0; mi < 4; mi++) {
        #pragma unroll
        for (int ni = 0; ni < 4; ni++) {
            int mg = m0 + wm0 + mi * 16 + r;
            int ng = n0 + wn0 + ni * 8 + cc;
            #pragma unroll
            for (int half_i = 0; half_i < 2; half_i++) {
                int m = mg + half_i * 8;
                float e = acc[mi][ni][half_i * 2 + 0];
                float o = acc[mi][ni][half_i * 2 + 1];
                if (QKV == 0) {
                    float2 v = {e, o};
                    *(float2*)&outF[(size_t)m * DMODEL + ng] = v;
                } else {
                    int h = ng >> 6, nh = ng & 63;
                    int b = m >> 11, s = m & (SEQ - 1);
                    size_t off = (((size_t)(b * NHEADS + h) * SEQ + s) << 6) + nh;
                    if (z < 2) {
                        float2 csn = rope[s * 32 + (nh >> 1)];
                        float re = e * csn.x - o * csn.y;
                        float ro = e * csn.y + o * csn.x;
                        split2h(re, ro, oH + off, oL + off);
                    } else {
                        split2h(e, o, oH + off, oL + off);
                    }
                }
            }
        }
    }
}

// ---------------------------------------------------------------------------
// HMMA flash attention, causal. Q/K split fp16 (3-product QK), V split fp16,
// P plain fp16 (2-product PV). Output plain fp16 [b, s, 1024].
// CTA: 128 q rows, 8 warps; 64-key blocks; cp.async double buffer.
// ---------------------------------------------------------------------------
__global__ __launch_bounds__(256)
void attn_mma(const half* __restrict__ Qh, const half* __restrict__ Ql,
              const half* __restrict__ Kh, const half* __restrict__ Kl,
              const half* __restrict__ Vh, const half* __restrict__ Vl,
              half* __restrict__ outA)
{
    extern __shared__ char smem[];
    const uint32_t sb = smem_u32(smem);
    const int tid = threadIdx.x, warp = tid >> 5, lane = tid & 31;
    const int g = lane >> 2, t = lane & 3;
    const int qb = (int)gridDim.x - 1 - (int)blockIdx.x;   // heavy CTAs first
    const int bh = blockIdx.y;
    const size_t bhoff = (size_t)bh * SEQ * HDIM;
    const int qrow0 = qb * 128 + warp * 16;

    uint32_t qa_h[4][4], qa_l[4][4];
    {
        const half* Qbh = Qh + bhoff + (size_t)qrow0 * 64;
        const half* Qbl = Ql + bhoff + (size_t)qrow0 * 64;
        #pragma unroll
        for (int u = 0; u < 4; u++) {
            int c0 = u * 16 + 2 * t;
            qa_h[u][0] = *(const uint32_t*)(Qbh + (g    ) * 64 + c0);
            qa_h[u][1] = *(const uint32_t*)(Qbh + (g + 8) * 64 + c0);
            qa_h[u][2] = *(const uint32_t*)(Qbh + (g    ) * 64 + c0 + 8);
            qa_h[u][3] = *(const uint32_t*)(Qbh + (g + 8) * 64 + c0 + 8);
            qa_l[u][0] = *(const uint32_t*)(Qbl + (g    ) * 64 + c0);
            qa_l[u][1] = *(const uint32_t*)(Qbl + (g + 8) * 64 + c0);
            qa_l[u][2] = *(const uint32_t*)(Qbl + (g    ) * 64 + c0 + 8);
            qa_l[u][3] = *(const uint32_t*)(Qbl + (g + 8) * 64 + c0 + 8);
        }
    }

    float accO[8][4];
    #pragma unroll
    for (int i = 0; i < 8; i++)
        #pragma unroll
        for (int j = 0; j < 4; j++) accO[i][j] = 0.f;
    float m0 = -1e38f, m1 = -1e38f, l0 = 0.f, l1 = 0.f;

    const int nkb = 2 * qb + 2;
    const half* srcs[4] = {Kh + bhoff, Kl + bhoff, Vh + bhoff, Vl + bhoff};

    auto issue = [&](int buf, int kb) {
        #pragma unroll
        for (int it = 0; it < 8; it++) {
            int j = it * 256 + tid;
            int tile = j >> 9, v = j & 511, row = v >> 3, c = v & 7;
            const half* gp = srcs[tile] + (((size_t)(kb * 64 + row)) << 6) + c * 8;
            uint32_t sa = sb + buf * ASTAGE + tile * ATILE_B + row * 144 + c * 16;
            CP16(sa, gp);
        }
        CPCOMMIT();
    };

    issue(0, 0);

    for (int kb = 0; kb < nkb; kb++) {
        if (kb + 1 < nkb) { issue((kb + 1) & 1, kb + 1); CPWAIT1(); }
        else              { CPWAIT0(); }
        __syncthreads();

        const uint32_t base = sb + (kb & 1) * ASTAGE;

        // ---- S = Q K^T: QhKh + QhKl + QlKh ----
        float S[8][4];
        #pragma unroll
        for (int i = 0; i < 8; i++)
            #pragma unroll
            for (int j = 0; j < 4; j++) S[i][j] = 0.f;

        #pragma unroll
        for (int nt = 0; nt < 8; nt++) {
            #pragma unroll
            for (int u = 0; u < 4; u++) {
                uint32_t off = (nt * 8 + (lane & 7)) * 144 + (u * 16 + ((lane >> 3) & 1) * 8) * 2;
                uint32_t kh2[2], kl2[2];
                LDMX2(kh2, base + 0 * ATILE_B + off);
                LDMX2(kl2, base + 1 * ATILE_B + off);
                MMA16816(S[nt], qa_h[u], kh2);
                MMA16816(S[nt], qa_h[u], kl2);
                MMA16816(S[nt], qa_l[u], kh2);
            }
        }

        // ---- causal mask (diagonal blocks only) ----
        if (kb * 64 + 63 > qrow0) {
            #pragma unroll
            for (int nt = 0; nt < 8; nt++) {
                int key = kb * 64 + nt * 8 + 2 * t;
                int r0 = qrow0 + g, r1 = r0 + 8;
                if (key     > r0) S[nt][0] = -1e30f;
                if (key + 1 > r0) S[nt][1] = -1e30f;
                if (key     > r1) S[nt][2] = -1e30f;
                if (key + 1 > r1) S[nt][3] = -1e30f;
            }
        }

        // ---- online softmax ----
        float mx0 = -1e38f, mx1 = -1e38f;
        #pragma unroll
        for (int nt = 0; nt < 8; nt++) {
            mx0 = fmaxf(mx0, fmaxf(S[nt][0], S[nt][1]));
            mx1 = fmaxf(mx1, fmaxf(S[nt][2], S[nt][3]));
        }
        mx0 = fmaxf(mx0, __shfl_xor_sync(0xffffffffu, mx0, 1));
        mx0 = fmaxf(mx0, __shfl_xor_sync(0xffffffffu, mx0, 2));
        mx1 = fmaxf(mx1, __shfl_xor_sync(0xffffffffu, mx1, 1));
        mx1 = fmaxf(mx1, __shfl_xor_sync(0xffffffffu, mx1, 2));
        float mN0 = fmaxf(m0, mx0), mN1 = fmaxf(m1, mx1);
        float sc0 = ex2((m0 - mN0) * C_SCALE);
        float sc1 = ex2((m1 - mN1) * C_SCALE);
        m0 = mN0; m1 = mN1;
        l0 *= sc0; l1 *= sc1;
        #pragma unroll
        for (int nt = 0; nt < 8; nt++) {
            accO[nt][0] *= sc0; accO[nt][1] *= sc0;
            accO[nt][2] *= sc1; accO[nt][3] *= sc1;
        }

        // ---- p = exp2((s-m)*C), l accum, plain fp16 pack ----
        uint32_t Ph[8][2];
        #pragma unroll
        for (int nt = 0; nt < 8; nt++) {
            float p0 = ex2((S[nt][0] - m0) * C_SCALE);
            float p1 = ex2((S[nt][1] - m0) * C_SCALE);
            float p2 = ex2((S[nt][2] - m1) * C_SCALE);
            float p3 = ex2((S[nt][3] - m1) * C_SCALE);
            l0 += p0 + p1;
            l1 += p2 + p3;
            half2 h01 = __floats2half2_rn(p0, p1);
            half2 h23 = __floats2half2_rn(p2, p3);
            Ph[nt][0] = *(uint32_t*)&h01; Ph[nt][1] = *(uint32_t*)&h23;
        }

        // ---- O += P V: P·Vh + P·Vl ----
        #pragma unroll
        for (int u = 0; u < 4; u++) {
            uint32_t aph[4] = {Ph[2*u][0], Ph[2*u][1], Ph[2*u+1][0], Ph[2*u+1][1]};
            #pragma unroll
            for (int nt = 0; nt < 8; nt++) {
                uint32_t voff = (u * 16 + (lane & 15)) * 144 + nt * 8 * 2;
                uint32_t vh2[2], vl2[2];
                LDMX2T(vh2, base + 2 * ATILE_B + voff);
                LDMX2T(vl2, base + 3 * ATILE_B + voff);
                MMA16816(accO[nt], aph, vh2);
                MMA16816(accO[nt], aph, vl2);
            }
        }
        __syncthreads();
    }

    // ---- finalize ----
    l0 += __shfl_xor_sync(0xffffffffu, l0, 1);
    l0 += __shfl_xor_sync(0xffffffffu, l0, 2);
    l1 += __shfl_xor_sync(0xffffffffu, l1, 1);
    l1 += __shfl_xor_sync(0xffffffffu, l1, 2);
    float inv0 = 1.0f / l0, inv1 = 1.0f / l1;

    const int b = bh >> 4, h = bh & 15;
    const int s0 = qrow0 + g, s1 = s0 + 8;
    #pragma unroll
    for (int nt = 0; nt < 8; nt++) {
        int col = h * 64 + nt * 8 + 2 * t;
        size_t i0 = ((size_t)(b * SEQ + s0)) * DMODEL + col;
        size_t i1 = ((size_t)(b * SEQ + s1)) * DMODEL + col;
        half2 o0 = __floats2half2_rn(accO[nt][0] * inv0, accO[nt][1] * inv0);
        half2 o1 = __floats2half2_rn(accO[nt][2] * inv1, accO[nt][3] * inv1);
        *(half2*)(outA + i0) = o0;
        *(half2*)(outA + i1) = o1;
    }
}

// ---------------------------------------------------------------------------
extern "C" void kernel_launch(void* const* d_in, const int* in_sizes, int n_in,
                              void* d_out, int out_size)
{
    const float* x   = (const float*)d_in[0];
    const float* Wq  = (const float*)d_in[1];
    const float* Wk  = (const float*)d_in[2];
    const float* Wv  = (const float*)d_in[3];
    const float* Wo  = (const float*)d_in[4];
    const int*   pos = (const int*)d_in[6];
    float* out       = (float*)d_out;

    half *x16, *wh, *wl, *qh, *ql, *kh, *kl, *vh, *vl, *a16;
    float2* rtab;
    cudaGetSymbolAddress((void**)&x16, g_x16);
    cudaGetSymbolAddress((void**)&wh, g_wh);  cudaGetSymbolAddress((void**)&wl, g_wl);
    cudaGetSymbolAddress((void**)&qh, g_Qh);  cudaGetSymbolAddress((void**)&ql, g_Ql);
    cudaGetSymbolAddress((void**)&kh, g_Kh);  cudaGetSymbolAddress((void**)&kl, g_Kl);
    cudaGetSymbolAddress((void**)&vh, g_Vh);  cudaGetSymbolAddress((void**)&vl, g_Vl);
    cudaGetSymbolAddress((void**)&a16, g_a16);
    cudaGetSymbolAddress((void**)&rtab, g_rope);

    cudaFuncSetAttribute(gemm2<0>, cudaFuncAttributeMaxDynamicSharedMemorySize, SMEM_G);
    cudaFuncSetAttribute(gemm2<1>, cudaFuncAttributeMaxDynamicSharedMemorySize, SMEM_G);
    cudaFuncSetAttribute(attn_mma, cudaFuncAttributeMaxDynamicSharedMemorySize, ASMEM);

    const int NX4 = MTOT * DMODEL / 4;       // 1048576
    const int NW4 = DMODEL * DMODEL / 4;     // 262144
    const size_t WS = (size_t)DMODEL * DMODEL;

    conv_f16<<<NX4 / 256, 256>>>(x, x16, NX4);
    {
        dim3 gw(NW4 / 256, 1, 4);
        split_w<<<gw, 256>>>(Wq, Wk, Wv, Wo, wh, wl, NW4);
    }
    rope_tab<<<(SEQ * 32) / 256, 256>>>(pos, rtab);

    dim3 gq(DMODEL / BN, MTOT / BM, 3);      // (8, 32, 3) = 768 CTAs
    gemm2<1><<<gq, 256, SMEM_G>>>(x16, wh, wl, nullptr, qh, ql, kh, kl, vh, vl, rtab);

    dim3 ga(SEQ / 128, BATCH * NHEADS);      // (16, 32) = 512 CTAs
    attn_mma<<<ga, 256, ASMEM>>>(qh, ql, kh, kl, vh, vl, a16);

    dim3 go(DMODEL / BN, MTOT / BM, 1);      // (8, 32)
    gemm2<0><<<go, 256, SMEM_G>>>(a16, wh + 3 * WS, wl + 3 * WS, out,
                                  nullptr, nullptr, nullptr, nullptr, nullptr, nullptr, rtab);
}

// round 10
// speedup vs baseline: 4.7216x; 1.0115x over previous
#include <cuda_runtime.h>
#include <cuda_fp16.h>
#include <math.h>
#include <stdint.h>

#define BATCH   2
#define SEQ     2048
#define DMODEL  1024
#define NHEADS  16
#define HDIM    64
#define MTOT    (BATCH*SEQ)           // 4096
#define LOG2_THETA 13.28771238f       // log2(10000)
#define C_SCALE 0.18033688f           // log2(e)/8

// ---- GEMM tiling: A fp16, B split hi/lo fp16; BK=32, 3-stage ring ----
#define BM 128
#define BN 128
#define BKE 32
#define ROWB 80                        // 32 elems*2B + 16B pad; conflict-free ldmatrix
#define TILE_B (128*ROWB)              // 10240
#define STAGE3 (3*TILE_B)              // 30720
#define NSTAGE 3
#define SMEM_G (NSTAGE*STAGE3)         // 92160  -> 2 CTAs/SM

// ---- attention tiling (Kh,Kl,Vh,Vl tiles) ----
#define ATILE_B (64*144)               // 9216
#define ASTAGE  (4*ATILE_B)            // 36864
#define ASMEM   (2*ASTAGE)             // 73728

// ---- scratch ----
__device__ half g_x16[MTOT*DMODEL];
__device__ half g_wh[4][DMODEL*DMODEL], g_wl[4][DMODEL*DMODEL];
__device__ half g_Qh[BATCH*NHEADS*SEQ*HDIM], g_Ql[BATCH*NHEADS*SEQ*HDIM];
__device__ half g_Kh[BATCH*NHEADS*SEQ*HDIM], g_Kl[BATCH*NHEADS*SEQ*HDIM];
__device__ half g_Vh[BATCH*NHEADS*SEQ*HDIM], g_Vl[BATCH*NHEADS*SEQ*HDIM];
__device__ half g_a16[MTOT*DMODEL];
__device__ float2 g_rope[SEQ*32];

// ---------------------------------------------------------------------------
__device__ __forceinline__ uint32_t smem_u32(const void* p) {
    uint32_t a;
    asm("{ .reg .u64 t; cvta.to.shared.u64 t, %1; cvt.u32.u64 %0, t; }" : "=r"(a) : "l"(p));
    return a;
}
#define CP16(s, g)  asm volatile("cp.async.cg.shared.global [%0], [%1], 16;" :: "r"(s), "l"(g))
#define CPCOMMIT()  asm volatile("cp.async.commit_group;" ::: "memory")
#define CPWAIT0()   asm volatile("cp.async.wait_group 0;" ::: "memory")
#define CPWAIT1()   asm volatile("cp.async.wait_group 1;" ::: "memory")

#define LDMX4(r, a) asm volatile("ldmatrix.sync.aligned.m8n8.x4.shared.b16 {%0,%1,%2,%3}, [%4];" \
    : "=r"((r)[0]), "=r"((r)[1]), "=r"((r)[2]), "=r"((r)[3]) : "r"(a))
#define LDMX2(r, a) asm volatile("ldmatrix.sync.aligned.m8n8.x2.shared.b16 {%0,%1}, [%2];" \
    : "=r"((r)[0]), "=r"((r)[1]) : "r"(a))
#define LDMX2T(r, a) asm volatile("ldmatrix.sync.aligned.m8n8.x2.trans.shared.b16 {%0,%1}, [%2];" \
    : "=r"((r)[0]), "=r"((r)[1]) : "r"(a))

#define MMA16816(c, a, b) asm volatile( \
    "mma.sync.aligned.m16n8k16.row.col.f32.f16.f16.f32 " \
    "{%0,%1,%2,%3},{%4,%5,%6,%7},{%8,%9},{%0,%1,%2,%3};" \
    : "+f"((c)[0]), "+f"((c)[1]), "+f"((c)[2]), "+f"((c)[3]) \
    : "r"((a)[0]), "r"((a)[1]), "r"((a)[2]), "r"((a)[3]), "r"((b)[0]), "r"((b)[1]))

__device__ __forceinline__ float ex2(float x) {
    float r; asm("ex2.approx.ftz.f32 %0, %1;" : "=f"(r) : "f"(x)); return r;
}
__device__ __forceinline__ void split2h(float v0, float v1, half* ph, half* pl) {
    half h0 = __float2half_rn(v0), h1 = __float2half_rn(v1);
    half l0 = __float2half_rn(v0 - __half2float(h0));
    half l1 = __float2half_rn(v1 - __half2float(h1));
    half2 hv = {h0, h1}, lv = {l0, l1};
    *(half2*)ph = hv;
    *(half2*)pl = lv;
}

// ---------------------------------------------------------------------------
// conversions
// ---------------------------------------------------------------------------
__global__ __launch_bounds__(256)
void conv_f16(const float* __restrict__ in, half* __restrict__ out, int n4)
{
    int i = blockIdx.x * 256 + threadIdx.x;
    if (i >= n4) return;
    float4 v = ((const float4*)in)[i];
    half2 a = __floats2half2_rn(v.x, v.y);
    half2 b = __floats2half2_rn(v.z, v.w);
    uint2 u;
    u.x = *(uint32_t*)&a; u.y = *(uint32_t*)&b;
    ((uint2*)out)[i] = u;
}

__global__ __launch_bounds__(256)
void split_w(const float* __restrict__ w0, const float* __restrict__ w1,
             const float* __restrict__ w2, const float* __restrict__ w3,
             half* __restrict__ hi, half* __restrict__ lo, int n4)
{
    int z = blockIdx.z;
    const float* w = (z == 0) ? w0 : (z == 1) ? w1 : (z == 2) ? w2 : w3;
    int i = blockIdx.x * 256 + threadIdx.x;
    if (i >= n4) return;
    float4 v = ((const float4*)w)[i];
    size_t base = (size_t)z * DMODEL * DMODEL / 4;
    half h0 = __float2half_rn(v.x), h1 = __float2half_rn(v.y);
    half h2 = __float2half_rn(v.z), h3 = __float2half_rn(v.w);
    half2 hA = {h0, h1}, hB = {h2, h3};
    half2 lA = {__float2half_rn(v.x - __half2float(h0)), __float2half_rn(v.y - __half2float(h1))};
    half2 lB = {__float2half_rn(v.z - __half2float(h2)), __float2half_rn(v.w - __half2float(h3))};
    uint2 uh, ul;
    uh.x = *(uint32_t*)&hA; uh.y = *(uint32_t*)&hB;
    ul.x = *(uint32_t*)&lA; ul.y = *(uint32_t*)&lB;
    ((uint2*)hi)[base + i] = uh;
    ((uint2*)lo)[base + i] = ul;
}

__global__ __launch_bounds__(256)
void rope_tab(const int* __restrict__ posarr, float2* __restrict__ tab)
{
    int i = blockIdx.x * 256 + threadIdx.x;
    int s = i >> 5, f = i & 31;
    float pos = (float)posarr[s];
    float fr = exp2f(-LOG2_THETA * (float)f * (1.0f / 32.0f));
    float sn, cs;
    sincosf(pos * fr, &sn, &cs);
    tab[i] = make_float2(cs, sn);
}

// ---------------------------------------------------------------------------
// 2-product fp16 HMMA GEMM, BK=32, 3-stage, 2 CTAs/SM.
// QKV=1: fused Q/K/V via blockIdx.z; QKV=0: O projection (fp32 out)
// ---------------------------------------------------------------------------
template<int QKV>
__global__ __launch_bounds__(256, 2)
void gemm2(const half* __restrict__ A, const half* __restrict__ Wh0,
           const half* __restrict__ Wl0, float* __restrict__ outF,
           half* __restrict__ qh, half* __restrict__ ql,
           half* __restrict__ kh, half* __restrict__ kl,
           half* __restrict__ vh, half* __restrict__ vl,
           const float2* __restrict__ rope)
{
    extern __shared__ char smem[];
    const uint32_t sb = smem_u32(smem);
    const int tid  = threadIdx.x;
    const int warp = tid >> 5;
    const int lane = tid & 31;
    const int m0 = blockIdx.y * BM;
    const int n0 = blockIdx.x * BN;
    const int z  = QKV ? blockIdx.z : 0;
    const int wm0 = (warp >> 2) * 64;
    const int wn0 = (warp & 3) * 32;

    float acc[4][4][4];
    #pragma unroll
    for (int i = 0; i < 4; i++)
        #pragma unroll
        for (int j = 0; j < 4; j++)
            #pragma unroll
            for (int k = 0; k < 4; k++) acc[i][j][k] = 0.f;

    const size_t WS = (size_t)DMODEL * DMODEL;
    const half* srcs[3] = {
        A + (size_t)m0 * DMODEL,
        Wh0 + (size_t)z * WS + (size_t)n0 * DMODEL,
        Wl0 + (size_t)z * WS + (size_t)n0 * DMODEL
    };

    // stage = 3 tiles x 128 rows x 32 elems = 1536 x 16B vecs, 6/thread
    auto issue = [&](int buf, int chunk) {
        const int kof = chunk * BKE;
        #pragma unroll
        for (int t = 0; t < 6; t++) {
            int j = t * 256 + tid;
            int tile = j >> 9;
            int v = j & 511;
            int row = v >> 2, c = v & 3;
            const half* g = srcs[tile] + (size_t)row * DMODEL + kof + c * 8;
            uint32_t s = sb + buf * STAGE3 + tile * TILE_B + row * ROWB + c * 16;
            CP16(s, g);
        }
        CPCOMMIT();
    };

    issue(0, 0);
    issue(1, 1);

    const int NCH = DMODEL / BKE;       // 32
    for (int i = 0; i < NCH; i++) {
        if (i < NCH - 2) CPWAIT1(); else if (i == NCH - 2) CPWAIT1(); else CPWAIT0();
        __syncthreads();
        if (i + 2 < NCH) issue((i + 2) % NSTAGE, i + 2);

        const uint32_t base = sb + (i % NSTAGE) * STAGE3;
        #pragma unroll
        for (int ks = 0; ks < 2; ks++) {
            uint32_t af[4][4], bh[4][2], bl[4][2];
            const int arow = wm0 + (lane & 15);
            const int acolB = (ks * 16 + (lane >> 4) * 8) * 2;
            #pragma unroll
            for (int mi = 0; mi < 4; mi++)
                LDMX4(af[mi], base + (arow + mi * 16) * ROWB + acolB);
            const int brow = wn0 + (lane & 7);
            const int bcolB = (ks * 16 + ((lane >> 3) & 1) * 8) * 2;
            #pragma unroll
            for (int ni = 0; ni < 4; ni++) {
                uint32_t off = (brow + ni * 8) * ROWB + bcolB;
                LDMX2(bh[ni], base + 1 * TILE_B + off);
                LDMX2(bl[ni], base + 2 * TILE_B + off);
            }
            #pragma unroll
            for (int mi = 0; mi < 4; mi++)
                #pragma unroll
                for (int ni = 0; ni < 4; ni++) {
                    MMA16816(acc[mi][ni], af[mi], bh[ni]);
                    MMA16816(acc[mi][ni], af[mi], bl[ni]);
                }
        }
        __syncthreads();
    }

    const int r = lane >> 2;
    const int cc = (lane & 3) * 2;
    half* oH = (z == 0) ? qh : (z == 1) ? kh : vh;
    half* oL = (z == 0) ? ql : (z == 1) ? kl : vl;
    #pragma unroll
    for (int mi = 0; mi < 4; mi++) {
        #pragma unroll
        for (int ni = 0; ni < 4; ni++) {
            int mg = m0 + wm0 + mi * 16 + r;
            int ng = n0 + wn0 + ni * 8 + cc;
            #pragma unroll
            for (int half_i = 0; half_i < 2; half_i++) {
                int m = mg + half_i * 8;
                float e = acc[mi][ni][half_i * 2 + 0];
                float o = acc[mi][ni][half_i * 2 + 1];
                if (QKV == 0) {
                    float2 v = {e, o};
                    *(float2*)&outF[(size_t)m * DMODEL + ng] = v;
                } else {
                    int h = ng >> 6, nh = ng & 63;
                    int b = m >> 11, s = m & (SEQ - 1);
                    size_t off = (((size_t)(b * NHEADS + h) * SEQ + s) << 6) + nh;
                    if (z < 2) {
                        float2 csn = rope[s * 32 + (nh >> 1)];
                        float re = e * csn.x - o * csn.y;
                        float ro = e * csn.y + o * csn.x;
                        split2h(re, ro, oH + off, oL + off);
                    } else {
                        split2h(e, o, oH + off, oL + off);
                    }
                }
            }
        }
    }
}

// ---------------------------------------------------------------------------
// HMMA flash attention (unchanged from R8 winner).
// ---------------------------------------------------------------------------
__global__ __launch_bounds__(256)
void attn_mma(const half* __restrict__ Qh, const half* __restrict__ Ql,
              const half* __restrict__ Kh, const half* __restrict__ Kl,
              const half* __restrict__ Vh, const half* __restrict__ Vl,
              half* __restrict__ outA)
{
    extern __shared__ char smem[];
    const uint32_t sb = smem_u32(smem);
    const int tid = threadIdx.x, warp = tid >> 5, lane = tid & 31;
    const int g = lane >> 2, t = lane & 3;
    const int qb = (int)gridDim.x - 1 - (int)blockIdx.x;
    const int bh = blockIdx.y;
    const size_t bhoff = (size_t)bh * SEQ * HDIM;
    const int qrow0 = qb * 128 + warp * 16;

    uint32_t qa_h[4][4], qa_l[4][4];
    {
        const half* Qbh = Qh + bhoff + (size_t)qrow0 * 64;
        const half* Qbl = Ql + bhoff + (size_t)qrow0 * 64;
        #pragma unroll
        for (int u = 0; u < 4; u++) {
            int c0 = u * 16 + 2 * t;
            qa_h[u][0] = *(const uint32_t*)(Qbh + (g    ) * 64 + c0);
            qa_h[u][1] = *(const uint32_t*)(Qbh + (g + 8) * 64 + c0);
            qa_h[u][2] = *(const uint32_t*)(Qbh + (g    ) * 64 + c0 + 8);
            qa_h[u][3] = *(const uint32_t*)(Qbh + (g + 8) * 64 + c0 + 8);
            qa_l[u][0] = *(const uint32_t*)(Qbl + (g    ) * 64 + c0);
            qa_l[u][1] = *(const uint32_t*)(Qbl + (g + 8) * 64 + c0);
            qa_l[u][2] = *(const uint32_t*)(Qbl + (g    ) * 64 + c0 + 8);
            qa_l[u][3] = *(const uint32_t*)(Qbl + (g + 8) * 64 + c0 + 8);
        }
    }

    float accO[8][4];
    #pragma unroll
    for (int i = 0; i < 8; i++)
        #pragma unroll
        for (int j = 0; j < 4; j++) accO[i][j] = 0.f;
    float m0 = -1e38f, m1 = -1e38f, l0 = 0.f, l1 = 0.f;

    const int nkb = 2 * qb + 2;
    const half* srcs[4] = {Kh + bhoff, Kl + bhoff, Vh + bhoff, Vl + bhoff};

    auto issue = [&](int buf, int kb) {
        #pragma unroll
        for (int it = 0; it < 8; it++) {
            int j = it * 256 + tid;
            int tile = j >> 9, v = j & 511, row = v >> 3, c = v & 7;
            const half* gp = srcs[tile] + (((size_t)(kb * 64 + row)) << 6) + c * 8;
            uint32_t sa = sb + buf * ASTAGE + tile * ATILE_B + row * 144 + c * 16;
            CP16(sa, gp);
        }
        CPCOMMIT();
    };

    issue(0, 0);

    for (int kb = 0; kb < nkb; kb++) {
        if (kb + 1 < nkb) { issue((kb + 1) & 1, kb + 1); CPWAIT1(); }
        else              { CPWAIT0(); }
        __syncthreads();

        const uint32_t base = sb + (kb & 1) * ASTAGE;

        float S[8][4];
        #pragma unroll
        for (int i = 0; i < 8; i++)
            #pragma unroll
            for (int j = 0; j < 4; j++) S[i][j] = 0.f;

        #pragma unroll
        for (int nt = 0; nt < 8; nt++) {
            #pragma unroll
            for (int u = 0; u < 4; u++) {
                uint32_t off = (nt * 8 + (lane & 7)) * 144 + (u * 16 + ((lane >> 3) & 1) * 8) * 2;
                uint32_t kh2[2], kl2[2];
                LDMX2(kh2, base + 0 * ATILE_B + off);
                LDMX2(kl2, base + 1 * ATILE_B + off);
                MMA16816(S[nt], qa_h[u], kh2);
                MMA16816(S[nt], qa_h[u], kl2);
                MMA16816(S[nt], qa_l[u], kh2);
            }
        }

        if (kb * 64 + 63 > qrow0) {
            #pragma unroll
            for (int nt = 0; nt < 8; nt++) {
                int key = kb * 64 + nt * 8 + 2 * t;
                int r0 = qrow0 + g, r1 = r0 + 8;
                if (key     > r0) S[nt][0] = -1e30f;
                if (key + 1 > r0) S[nt][1] = -1e30f;
                if (key     > r1) S[nt][2] = -1e30f;
                if (key + 1 > r1) S[nt][3] = -1e30f;
            }
        }

        float mx0 = -1e38f, mx1 = -1e38f;
        #pragma unroll
        for (int nt = 0; nt < 8; nt++) {
            mx0 = fmaxf(mx0, fmaxf(S[nt][0], S[nt][1]));
            mx1 = fmaxf(mx1, fmaxf(S[nt][2], S[nt][3]));
        }
        mx0 = fmaxf(mx0, __shfl_xor_sync(0xffffffffu, mx0, 1));
        mx0 = fmaxf(mx0, __shfl_xor_sync(0xffffffffu, mx0, 2));
        mx1 = fmaxf(mx1, __shfl_xor_sync(0xffffffffu, mx1, 1));
        mx1 = fmaxf(mx1, __shfl_xor_sync(0xffffffffu, mx1, 2));
        float mN0 = fmaxf(m0, mx0), mN1 = fmaxf(m1, mx1);
        float sc0 = ex2((m0 - mN0) * C_SCALE);
        float sc1 = ex2((m1 - mN1) * C_SCALE);
        m0 = mN0; m1 = mN1;
        l0 *= sc0; l1 *= sc1;
        #pragma unroll
        for (int nt = 0; nt < 8; nt++) {
            accO[nt][0] *= sc0; accO[nt][1] *= sc0;
            accO[nt][2] *= sc1; accO[nt][3] *= sc1;
        }

        uint32_t Ph[8][2];
        #pragma unroll
        for (int nt = 0; nt < 8; nt++) {
            float p0 = ex2((S[nt][0] - m0) * C_SCALE);
            float p1 = ex2((S[nt][1] - m0) * C_SCALE);
            float p2 = ex2((S[nt][2] - m1) * C_SCALE);
            float p3 = ex2((S[nt][3] - m1) * C_SCALE);
            l0 += p0 + p1;
            l1 += p2 + p3;
            half2 h01 = __floats2half2_rn(p0, p1);
            half2 h23 = __floats2half2_rn(p2, p3);
            Ph[nt][0] = *(uint32_t*)&h01; Ph[nt][1] = *(uint32_t*)&h23;
        }

        #pragma unroll
        for (int u = 0; u < 4; u++) {
            uint32_t aph[4] = {Ph[2*u][0], Ph[2*u][1], Ph[2*u+1][0], Ph[2*u+1][1]};
            #pragma unroll
            for (int nt = 0; nt < 8; nt++) {
                uint32_t voff = (u * 16 + (lane & 15)) * 144 + nt * 8 * 2;
                uint32_t vh2[2], vl2[2];
                LDMX2T(vh2, base + 2 * ATILE_B + voff);
                LDMX2T(vl2, base + 3 * ATILE_B + voff);
                MMA16816(accO[nt], aph, vh2);
                MMA16816(accO[nt], aph, vl2);
            }
        }
        __syncthreads();
    }

    l0 += __shfl_xor_sync(0xffffffffu, l0, 1);
    l0 += __shfl_xor_sync(0xffffffffu, l0, 2);
    l1 += __shfl_xor_sync(0xffffffffu, l1, 1);
    l1 += __shfl_xor_sync(0xffffffffu, l1, 2);
    float inv0 = 1.0f / l0, inv1 = 1.0f / l1;

    const int b = bh >> 4, h = bh & 15;
    const int s0 = qrow0 + g, s1 = s0 + 8;
    #pragma unroll
    for (int nt = 0; nt < 8; nt++) {
        int col = h * 64 + nt * 8 + 2 * t;
        size_t i0 = ((size_t)(b * SEQ + s0)) * DMODEL + col;
        size_t i1 = ((size_t)(b * SEQ + s1)) * DMODEL + col;
        half2 o0 = __floats2half2_rn(accO[nt][0] * inv0, accO[nt][1] * inv0);
        half2 o1 = __floats2half2_rn(accO[nt][2] * inv1, accO[nt][3] * inv1);
        *(half2*)(outA + i0) = o0;
        *(half2*)(outA + i1) = o1;
    }
}

// ---------------------------------------------------------------------------
extern "C" void kernel_launch(void* const* d_in, const int* in_sizes, int n_in,
                              void* d_out, int out_size)
{
    const float* x   = (const float*)d_in[0];
    const float* Wq  = (const float*)d_in[1];
    const float* Wk  = (const float*)d_in[2];
    const float* Wv  = (const float*)d_in[3];
    const float* Wo  = (const float*)d_in[4];
    const int*   pos = (const int*)d_in[6];
    float* out       = (float*)d_out;

    half *x16, *wh, *wl, *qh, *ql, *kh, *kl, *vh, *vl, *a16;
    float2* rtab;
    cudaGetSymbolAddress((void**)&x16, g_x16);
    cudaGetSymbolAddress((void**)&wh, g_wh);  cudaGetSymbolAddress((void**)&wl, g_wl);
    cudaGetSymbolAddress((void**)&qh, g_Qh);  cudaGetSymbolAddress((void**)&ql, g_Ql);
    cudaGetSymbolAddress((void**)&kh, g_Kh);  cudaGetSymbolAddress((void**)&kl, g_Kl);
    cudaGetSymbolAddress((void**)&vh, g_Vh);  cudaGetSymbolAddress((void**)&vl, g_Vl);
    cudaGetSymbolAddress((void**)&a16, g_a16);
    cudaGetSymbolAddress((void**)&rtab, g_rope);

    cudaFuncSetAttribute(gemm2<0>, cudaFuncAttributeMaxDynamicSharedMemorySize, SMEM_G);
    cudaFuncSetAttribute(gemm2<1>, cudaFuncAttributeMaxDynamicSharedMemorySize, SMEM_G);
    cudaFuncSetAttribute(attn_mma, cudaFuncAttributeMaxDynamicSharedMemorySize, ASMEM);

    const int NX4 = MTOT * DMODEL / 4;
    const int NW4 = DMODEL * DMODEL / 4;
    const size_t WS = (size_t)DMODEL * DMODEL;

    conv_f16<<<NX4 / 256, 256>>>(x, x16, NX4);
    {
        dim3 gw(NW4 / 256, 1, 4);
        split_w<<<gw, 256>>>(Wq, Wk, Wv, Wo, wh, wl, NW4);
    }
    rope_tab<<<(SEQ * 32) / 256, 256>>>(pos, rtab);

    dim3 gq(DMODEL / BN, MTOT / BM, 3);      // (8, 32, 3) = 768 CTAs
    gemm2<1><<<gq, 256, SMEM_G>>>(x16, wh, wl, nullptr, qh, ql, kh, kl, vh, vl, rtab);

    dim3 ga(SEQ / 128, BATCH * NHEADS);      // (16, 32) = 512 CTAs
    attn_mma<<<ga, 256, ASMEM>>>(qh, ql, kh, kl, vh, vl, a16);

    dim3 go(DMODEL / BN, MTOT / BM, 1);      // (8, 32)
    gemm2<0><<<go, 256, SMEM_G>>>(a16, wh + 3 * WS, wl + 3 * WS, out,
                                  nullptr, nullptr, nullptr, nullptr, nullptr, nullptr, rtab);
}

// round 11
// speedup vs baseline: 6.7735x; 1.4346x over previous
#include <cuda_runtime.h>
#include <cuda_fp16.h>
#include <math.h>
#include <stdint.h>

#define BATCH   2
#define SEQ     2048
#define DMODEL  1024
#define NHEADS  16
#define HDIM    64
#define MTOT    (BATCH*SEQ)           // 4096
#define LOG2_THETA 13.28771238f       // log2(10000)
#define C_SCALE 0.18033688f           // log2(e)/8

// ---- GEMM tiling: A fp16, W plain fp16; BK=32, 3-stage ring ----
#define BM 128
#define BN 128
#define BKE 32
#define ROWB 80                        // 32 elems*2B + 16B pad
#define TILE_B (128*ROWB)              // 10240
#define STAGE2 (2*TILE_B)              // 20480  (A + W)
#define NSTAGE 3
#define SMEM_G (NSTAGE*STAGE2)         // 61440

// ---- attention tiling (Kh,Kl,Vh tiles) ----
#define ATILE_B (64*144)               // 9216
#define ASTAGE  (3*ATILE_B)            // 27648
#define ASMEM   (2*ASTAGE)             // 55296

// ---- scratch ----
__device__ half g_x16[MTOT*DMODEL];
__device__ half g_w16[4][DMODEL*DMODEL];
__device__ half g_Qh[BATCH*NHEADS*SEQ*HDIM], g_Ql[BATCH*NHEADS*SEQ*HDIM];
__device__ half g_Kh[BATCH*NHEADS*SEQ*HDIM], g_Kl[BATCH*NHEADS*SEQ*HDIM];
__device__ half g_Vh[BATCH*NHEADS*SEQ*HDIM];
__device__ half g_a16[MTOT*DMODEL];
__device__ float2 g_rope[SEQ*32];

// ---------------------------------------------------------------------------
__device__ __forceinline__ uint32_t smem_u32(const void* p) {
    uint32_t a;
    asm("{ .reg .u64 t; cvta.to.shared.u64 t, %1; cvt.u32.u64 %0, t; }" : "=r"(a) : "l"(p));
    return a;
}
#define CP16(s, g)  asm volatile("cp.async.cg.shared.global [%0], [%1], 16;" :: "r"(s), "l"(g))
#define CPCOMMIT()  asm volatile("cp.async.commit_group;" ::: "memory")
#define CPWAIT0()   asm volatile("cp.async.wait_group 0;" ::: "memory")
#define CPWAIT1()   asm volatile("cp.async.wait_group 1;" ::: "memory")

#define LDMX4(r, a) asm volatile("ldmatrix.sync.aligned.m8n8.x4.shared.b16 {%0,%1,%2,%3}, [%4];" \
    : "=r"((r)[0]), "=r"((r)[1]), "=r"((r)[2]), "=r"((r)[3]) : "r"(a))
#define LDMX2(r, a) asm volatile("ldmatrix.sync.aligned.m8n8.x2.shared.b16 {%0,%1}, [%2];" \
    : "=r"((r)[0]), "=r"((r)[1]) : "r"(a))
#define LDMX2T(r, a) asm volatile("ldmatrix.sync.aligned.m8n8.x2.trans.shared.b16 {%0,%1}, [%2];" \
    : "=r"((r)[0]), "=r"((r)[1]) : "r"(a))

#define MMA16816(c, a, b) asm volatile( \
    "mma.sync.aligned.m16n8k16.row.col.f32.f16.f16.f32 " \
    "{%0,%1,%2,%3},{%4,%5,%6,%7},{%8,%9},{%0,%1,%2,%3};" \
    : "+f"((c)[0]), "+f"((c)[1]), "+f"((c)[2]), "+f"((c)[3]) \
    : "r"((a)[0]), "r"((a)[1]), "r"((a)[2]), "r"((a)[3]), "r"((b)[0]), "r"((b)[1]))

__device__ __forceinline__ float ex2(float x) {
    float r; asm("ex2.approx.ftz.f32 %0, %1;" : "=f"(r) : "f"(x)); return r;
}
__device__ __forceinline__ void split2h(float v0, float v1, half* ph, half* pl) {
    half h0 = __float2half_rn(v0), h1 = __float2half_rn(v1);
    half l0 = __float2half_rn(v0 - __half2float(h0));
    half l1 = __float2half_rn(v1 - __half2float(h1));
    half2 hv = {h0, h1}, lv = {l0, l1};
    *(half2*)ph = hv;
    *(half2*)pl = lv;
}

// ---------------------------------------------------------------------------
// conversions
// ---------------------------------------------------------------------------
__global__ __launch_bounds__(256)
void conv_f16(const float* __restrict__ in, half* __restrict__ out, int n4)
{
    int i = blockIdx.x * 256 + threadIdx.x;
    if (i >= n4) return;
    float4 v = ((const float4*)in)[i];
    half2 a = __floats2half2_rn(v.x, v.y);
    half2 b = __floats2half2_rn(v.z, v.w);
    uint2 u;
    u.x = *(uint32_t*)&a; u.y = *(uint32_t*)&b;
    ((uint2*)out)[i] = u;
}

__global__ __launch_bounds__(256)
void conv_w(const float* __restrict__ w0, const float* __restrict__ w1,
            const float* __restrict__ w2, const float* __restrict__ w3,
            half* __restrict__ out, int n4)
{
    int z = blockIdx.z;
    const float* w = (z == 0) ? w0 : (z == 1) ? w1 : (z == 2) ? w2 : w3;
    int i = blockIdx.x * 256 + threadIdx.x;
    if (i >= n4) return;
    float4 v = ((const float4*)w)[i];
    half2 a = __floats2half2_rn(v.x, v.y);
    half2 b = __floats2half2_rn(v.z, v.w);
    uint2 u;
    u.x = *(uint32_t*)&a; u.y = *(uint32_t*)&b;
    ((uint2*)out)[(size_t)z * (DMODEL * DMODEL / 4) + i] = u;
}

__global__ __launch_bounds__(256)
void rope_tab(const int* __restrict__ posarr, float2* __restrict__ tab)
{
    int i = blockIdx.x * 256 + threadIdx.x;
    int s = i >> 5, f = i & 31;
    float pos = (float)posarr[s];
    float fr = exp2f(-LOG2_THETA * (float)f * (1.0f / 32.0f));
    float sn, cs;
    sincosf(pos * fr, &sn, &cs);
    tab[i] = make_float2(cs, sn);
}

// ---------------------------------------------------------------------------
// plain fp16 HMMA GEMM: C = A @ W^T;  BK=32, 3-stage, 1 product.
// QKV=1: fused Q/K/V via blockIdx.z (RoPE for z<2; Q,K stored split hi/lo,
//        V stored plain). QKV=0: O projection (fp32 out)
// ---------------------------------------------------------------------------
template<int QKV>
__global__ __launch_bounds__(256, 2)
void gemm2(const half* __restrict__ A, const half* __restrict__ W0,
           float* __restrict__ outF,
           half* __restrict__ qh, half* __restrict__ ql,
           half* __restrict__ kh, half* __restrict__ kl,
           half* __restrict__ vh,
           const float2* __restrict__ rope)
{
    extern __shared__ char smem[];
    const uint32_t sb = smem_u32(smem);
    const int tid  = threadIdx.x;
    const int warp = tid >> 5;
    const int lane = tid & 31;
    const int m0 = blockIdx.y * BM;
    const int n0 = blockIdx.x * BN;
    const int z  = QKV ? blockIdx.z : 0;
    const int wm0 = (warp >> 2) * 64;
    const int wn0 = (warp & 3) * 32;

    float acc[4][4][4];
    #pragma unroll
    for (int i = 0; i < 4; i++)
        #pragma unroll
        for (int j = 0; j < 4; j++)
            #pragma unroll
            for (int k = 0; k < 4; k++) acc[i][j][k] = 0.f;

    const size_t WS = (size_t)DMODEL * DMODEL;
    const half* srcs[2] = {
        A + (size_t)m0 * DMODEL,
        W0 + (size_t)z * WS + (size_t)n0 * DMODEL
    };

    // stage = 2 tiles x 128 rows x 32 elems = 1024 x 16B vecs, 4/thread
    auto issue = [&](int buf, int chunk) {
        const int kof = chunk * BKE;
        #pragma unroll
        for (int t = 0; t < 4; t++) {
            int j = t * 256 + tid;
            int tile = j >> 9;
            int v = j & 511;
            int row = v >> 2, c = v & 3;
            const half* g = srcs[tile] + (size_t)row * DMODEL + kof + c * 8;
            uint32_t s = sb + buf * STAGE2 + tile * TILE_B + row * ROWB + c * 16;
            CP16(s, g);
        }
        CPCOMMIT();
    };

    issue(0, 0);
    issue(1, 1);

    const int NCH = DMODEL / BKE;       // 32
    for (int i = 0; i < NCH; i++) {
        if (i < NCH - 1) CPWAIT1(); else CPWAIT0();
        __syncthreads();
        if (i + 2 < NCH) issue((i + 2) % NSTAGE, i + 2);

        const uint32_t base = sb + (i % NSTAGE) * STAGE2;
        #pragma unroll
        for (int ks = 0; ks < 2; ks++) {
            uint32_t af[4][4], bf[4][2];
            const int arow = wm0 + (lane & 15);
            const int acolB = (ks * 16 + (lane >> 4) * 8) * 2;
            #pragma unroll
            for (int mi = 0; mi < 4; mi++)
                LDMX4(af[mi], base + (arow + mi * 16) * ROWB + acolB);
            const int brow = wn0 + (lane & 7);
            const int bcolB = (ks * 16 + ((lane >> 3) & 1) * 8) * 2;
            #pragma unroll
            for (int ni = 0; ni < 4; ni++)
                LDMX2(bf[ni], base + 1 * TILE_B + (brow + ni * 8) * ROWB + bcolB);
            #pragma unroll
            for (int mi = 0; mi < 4; mi++)
                #pragma unroll
                for (int ni = 0; ni < 4; ni++)
                    MMA16816(acc[mi][ni], af[mi], bf[ni]);
        }
        __syncthreads();
    }

    const int r = lane >> 2;
    const int cc = (lane & 3) * 2;
    #pragma unroll
    for (int mi = 0; mi < 4; mi++) {
        #pragma unroll
        for (int ni = 0; ni < 4; ni++) {
            int mg = m0 + wm0 + mi * 16 + r;
            int ng = n0 + wn0 + ni * 8 + cc;
            #pragma unroll
            for (int half_i = 0; half_i < 2; half_i++) {
                int m = mg + half_i * 8;
                float e = acc[mi][ni][half_i * 2 + 0];
                float o = acc[mi][ni][half_i * 2 + 1];
                if (QKV == 0) {
                    float2 v = {e, o};
                    *(float2*)&outF[(size_t)m * DMODEL + ng] = v;
                } else {
                    int h = ng >> 6, nh = ng & 63;
                    int b = m >> 11, s = m & (SEQ - 1);
                    size_t off = (((size_t)(b * NHEADS + h) * SEQ + s) << 6) + nh;
                    if (z < 2) {
                        float2 csn = rope[s * 32 + (nh >> 1)];
                        float re = e * csn.x - o * csn.y;
                        float ro = e * csn.y + o * csn.x;
                        if (z == 0) split2h(re, ro, qh + off, ql + off);
                        else        split2h(re, ro, kh + off, kl + off);
                    } else {
                        half2 v = __floats2half2_rn(e, o);
                        *(half2*)(vh + off) = v;
                    }
                }
            }
        }
    }
}

// ---------------------------------------------------------------------------
// HMMA flash attention, causal. QK 3-product (split q/k), PV 1-product (Vh).
// ---------------------------------------------------------------------------
__global__ __launch_bounds__(256)
void attn_mma(const half* __restrict__ Qh, const half* __restrict__ Ql,
              const half* __restrict__ Kh, const half* __restrict__ Kl,
              const half* __restrict__ Vh,
              half* __restrict__ outA)
{
    extern __shared__ char smem[];
    const uint32_t sb = smem_u32(smem);
    const int tid = threadIdx.x, warp = tid >> 5, lane = tid & 31;
    const int g = lane >> 2, t = lane & 3;
    const int qb = (int)gridDim.x - 1 - (int)blockIdx.x;
    const int bh = blockIdx.y;
    const size_t bhoff = (size_t)bh * SEQ * HDIM;
    const int qrow0 = qb * 128 + warp * 16;

    uint32_t qa_h[4][4], qa_l[4][4];
    {
        const half* Qbh = Qh + bhoff + (size_t)qrow0 * 64;
        const half* Qbl = Ql + bhoff + (size_t)qrow0 * 64;
        #pragma unroll
        for (int u = 0; u < 4; u++) {
            int c0 = u * 16 + 2 * t;
            qa_h[u][0] = *(const uint32_t*)(Qbh + (g    ) * 64 + c0);
            qa_h[u][1] = *(const uint32_t*)(Qbh + (g + 8) * 64 + c0);
            qa_h[u][2] = *(const uint32_t*)(Qbh + (g    ) * 64 + c0 + 8);
            qa_h[u][3] = *(const uint32_t*)(Qbh + (g + 8) * 64 + c0 + 8);
            qa_l[u][0] = *(const uint32_t*)(Qbl + (g    ) * 64 + c0);
            qa_l[u][1] = *(const uint32_t*)(Qbl + (g + 8) * 64 + c0);
            qa_l[u][2] = *(const uint32_t*)(Qbl + (g    ) * 64 + c0 + 8);
            qa_l[u][3] = *(const uint32_t*)(Qbl + (g + 8) * 64 + c0 + 8);
        }
    }

    float accO[8][4];
    #pragma unroll
    for (int i = 0; i < 8; i++)
        #pragma unroll
        for (int j = 0; j < 4; j++) accO[i][j] = 0.f;
    float m0 = -1e38f, m1 = -1e38f, l0 = 0.f, l1 = 0.f;

    const int nkb = 2 * qb + 2;
    const half* srcs[3] = {Kh + bhoff, Kl + bhoff, Vh + bhoff};

    auto issue = [&](int buf, int kb) {
        #pragma unroll
        for (int it = 0; it < 6; it++) {
            int j = it * 256 + tid;
            int tile = j >> 9, v = j & 511, row = v >> 3, c = v & 7;
            const half* gp = srcs[tile] + (((size_t)(kb * 64 + row)) << 6) + c * 8;
            uint32_t sa = sb + buf * ASTAGE + tile * ATILE_B + row * 144 + c * 16;
            CP16(sa, gp);
        }
        CPCOMMIT();
    };

    issue(0, 0);

    for (int kb = 0; kb < nkb; kb++) {
        if (kb + 1 < nkb) { issue((kb + 1) & 1, kb + 1); CPWAIT1(); }
        else              { CPWAIT0(); }
        __syncthreads();

        const uint32_t base = sb + (kb & 1) * ASTAGE;

        float S[8][4];
        #pragma unroll
        for (int i = 0; i < 8; i++)
            #pragma unroll
            for (int j = 0; j < 4; j++) S[i][j] = 0.f;

        #pragma unroll
        for (int nt = 0; nt < 8; nt++) {
            #pragma unroll
            for (int u = 0; u < 4; u++) {
                uint32_t off = (nt * 8 + (lane & 7)) * 144 + (u * 16 + ((lane >> 3) & 1) * 8) * 2;
                uint32_t kh2[2], kl2[2];
                LDMX2(kh2, base + 0 * ATILE_B + off);
                LDMX2(kl2, base + 1 * ATILE_B + off);
                MMA16816(S[nt], qa_h[u], kh2);
                MMA16816(S[nt], qa_h[u], kl2);
                MMA16816(S[nt], qa_l[u], kh2);
            }
        }

        if (kb * 64 + 63 > qrow0) {
            #pragma unroll
            for (int nt = 0; nt < 8; nt++) {
                int key = kb * 64 + nt * 8 + 2 * t;
                int r0 = qrow0 + g, r1 = r0 + 8;
                if (key     > r0) S[nt][0] = -1e30f;
                if (key + 1 > r0) S[nt][1] = -1e30f;
                if (key     > r1) S[nt][2] = -1e30f;
                if (key + 1 > r1) S[nt][3] = -1e30f;
            }
        }

        float mx0 = -1e38f, mx1 = -1e38f;
        #pragma unroll
        for (int nt = 0; nt < 8; nt++) {
            mx0 = fmaxf(mx0, fmaxf(S[nt][0], S[nt][1]));
            mx1 = fmaxf(mx1, fmaxf(S[nt][2], S[nt][3]));
        }
        mx0 = fmaxf(mx0, __shfl_xor_sync(0xffffffffu, mx0, 1));
        mx0 = fmaxf(mx0, __shfl_xor_sync(0xffffffffu, mx0, 2));
        mx1 = fmaxf(mx1, __shfl_xor_sync(0xffffffffu, mx1, 1));
        mx1 = fmaxf(mx1, __shfl_xor_sync(0xffffffffu, mx1, 2));
        float mN0 = fmaxf(m0, mx0), mN1 = fmaxf(m1, mx1);
        float sc0 = ex2((m0 - mN0) * C_SCALE);
        float sc1 = ex2((m1 - mN1) * C_SCALE);
        m0 = mN0; m1 = mN1;
        l0 *= sc0; l1 *= sc1;
        #pragma unroll
        for (int nt = 0; nt < 8; nt++) {
            accO[nt][0] *= sc0; accO[nt][1] *= sc0;
            accO[nt][2] *= sc1; accO[nt][3] *= sc1;
        }

        uint32_t Ph[8][2];
        #pragma unroll
        for (int nt = 0; nt < 8; nt++) {
            float p0 = ex2((S[nt][0] - m0) * C_SCALE);
            float p1 = ex2((S[nt][1] - m0) * C_SCALE);
            float p2 = ex2((S[nt][2] - m1) * C_SCALE);
            float p3 = ex2((S[nt][3] - m1) * C_SCALE);
            l0 += p0 + p1;
            l1 += p2 + p3;
            half2 h01 = __floats2half2_rn(p0, p1);
            half2 h23 = __floats2half2_rn(p2, p3);
            Ph[nt][0] = *(uint32_t*)&h01; Ph[nt][1] = *(uint32_t*)&h23;
        }

        #pragma unroll
        for (int u = 0; u < 4; u++) {
            uint32_t aph[4] = {Ph[2*u][0], Ph[2*u][1], Ph[2*u+1][0], Ph[2*u+1][1]};
            #pragma unroll
            for (int nt = 0; nt < 8; nt++) {
                uint32_t voff = (u * 16 + (lane & 15)) * 144 + nt * 8 * 2;
                uint32_t vh2[2];
                LDMX2T(vh2, base + 2 * ATILE_B + voff);
                MMA16816(accO[nt], aph, vh2);
            }
        }
        __syncthreads();
    }

    l0 += __shfl_xor_sync(0xffffffffu, l0, 1);
    l0 += __shfl_xor_sync(0xffffffffu, l0, 2);
    l1 += __shfl_xor_sync(0xffffffffu, l1, 1);
    l1 += __shfl_xor_sync(0xffffffffu, l1, 2);
    float inv0 = 1.0f / l0, inv1 = 1.0f / l1;

    const int b = bh >> 4, h = bh & 15;
    const int s0 = qrow0 + g, s1 = s0 + 8;
    #pragma unroll
    for (int nt = 0; nt < 8; nt++) {
        int col = h * 64 + nt * 8 + 2 * t;
        size_t i0 = ((size_t)(b * SEQ + s0)) * DMODEL + col;
        size_t i1 = ((size_t)(b * SEQ + s1)) * DMODEL + col;
        half2 o0 = __floats2half2_rn(accO[nt][0] * inv0, accO[nt][1] * inv0);
        half2 o1 = __floats2half2_rn(accO[nt][2] * inv1, accO[nt][3] * inv1);
        *(half2*)(outA + i0) = o0;
        *(half2*)(outA + i1) = o1;
    }
}

// ---------------------------------------------------------------------------
extern "C" void kernel_launch(void* const* d_in, const int* in_sizes, int n_in,
                              void* d_out, int out_size)
{
    const float* x   = (const float*)d_in[0];
    const float* Wq  = (const float*)d_in[1];
    const float* Wk  = (const float*)d_in[2];
    const float* Wv  = (const float*)d_in[3];
    const float* Wo  = (const float*)d_in[4];
    const int*   pos = (const int*)d_in[6];
    float* out       = (float*)d_out;

    half *x16, *w16, *qh, *ql, *kh, *kl, *vh, *a16;
    float2* rtab;
    cudaGetSymbolAddress((void**)&x16, g_x16);
    cudaGetSymbolAddress((void**)&w16, g_w16);
    cudaGetSymbolAddress((void**)&qh, g_Qh);  cudaGetSymbolAddress((void**)&ql, g_Ql);
    cudaGetSymbolAddress((void**)&kh, g_Kh);  cudaGetSymbolAddress((void**)&kl, g_Kl);
    cudaGetSymbolAddress((void**)&vh, g_Vh);
    cudaGetSymbolAddress((void**)&a16, g_a16);
    cudaGetSymbolAddress((void**)&rtab, g_rope);

    cudaFuncSetAttribute(gemm2<0>, cudaFuncAttributeMaxDynamicSharedMemorySize, SMEM_G);
    cudaFuncSetAttribute(gemm2<1>, cudaFuncAttributeMaxDynamicSharedMemorySize, SMEM_G);
    cudaFuncSetAttribute(attn_mma, cudaFuncAttributeMaxDynamicSharedMemorySize, ASMEM);

    const int NX4 = MTOT * DMODEL / 4;
    const int NW4 = DMODEL * DMODEL / 4;
    const size_t WS = (size_t)DMODEL * DMODEL;

    conv_f16<<<NX4 / 256, 256>>>(x, x16, NX4);
    {
        dim3 gw(NW4 / 256, 1, 4);
        conv_w<<<gw, 256>>>(Wq, Wk, Wv, Wo, w16, NW4);
    }
    rope_tab<<<(SEQ * 32) / 256, 256>>>(pos, rtab);

    dim3 gq(DMODEL / BN, MTOT / BM, 3);      // (8, 32, 3) = 768 CTAs
    gemm2<1><<<gq, 256, SMEM_G>>>(x16, w16, nullptr, qh, ql, kh, kl, vh, rtab);

    dim3 ga(SEQ / 128, BATCH * NHEADS);      // (16, 32) = 512 CTAs
    attn_mma<<<ga, 256, ASMEM>>>(qh, ql, kh, kl, vh, a16);

    dim3 go(DMODEL / BN, MTOT / BM, 1);      // (8, 32)
    gemm2<0><<<go, 256, SMEM_G>>>(a16, w16 + 3 * WS, out,
                                  nullptr, nullptr, nullptr, nullptr, nullptr, rtab);
}